// round 6
// baseline (speedup 1.0000x reference)
#include <cuda_runtime.h>
#include <cuda_bf16.h>
#include <cstdint>
#include <math.h>

#define Bb 2
#define Tt 2048
#define Dd 2048
#define Hh 16
#define HD 128
#define HD2 64
#define D3 (3*Dd)

// ---------------- scratch (static device globals) ----------------------------
__device__ float g_qkv[(size_t)Bb*Tt*D3];                 // [B,T,(q|k|v),D]
__device__ float g_att[(size_t)Bb*Tt*Dd];                 // attention output
__device__ __nv_bfloat16 g_xs [(size_t)Bb*Tt*2*Dd];       // x split   [M, 2K]
__device__ __nv_bfloat16 g_as [(size_t)Bb*Tt*2*Dd];       // att split [M, 2K]
__device__ __nv_bfloat16 g_ws1[(size_t)D3*2*Dd];          // w_attn split [N, 2K]
__device__ __nv_bfloat16 g_ws2[(size_t)Dd*2*Dd];          // w_proj split [N, 2K]
__device__ __nv_bfloat16 g_qs [(size_t)Bb*Hh*Tt*2*HD];    // q roped+scaled split [b,h,t,256]
__device__ __nv_bfloat16 g_ks [(size_t)Bb*Hh*Tt*2*HD];    // k roped split       [b,h,t,256]
__device__ __nv_bfloat16 g_vt [(size_t)Bb*Hh*HD*2*Tt];    // v^T split           [b,h,d,4096]

// ---------------- PTX helpers ------------------------------------------------
__device__ __forceinline__ uint32_t smem_u32(const void* p) {
    uint32_t a;
    asm("{ .reg .u64 t; cvta.to.shared.u64 t, %1; cvt.u32.u64 %0, t; }"
        : "=r"(a) : "l"(p));
    return a;
}
__device__ __forceinline__ void cp16(uint32_t s, const void* g) {
    asm volatile("cp.async.cg.shared.global [%0], [%1], 16;" :: "r"(s), "l"(g));
}
#define CP_COMMIT() asm volatile("cp.async.commit_group;" ::: "memory")
#define CP_WAIT(n)  asm volatile("cp.async.wait_group %0;" :: "n"(n) : "memory")

#define LDSM4(r, a) \
    asm volatile("ldmatrix.sync.aligned.m8n8.x4.shared.b16 {%0,%1,%2,%3}, [%4];" \
        : "=r"((r)[0]), "=r"((r)[1]), "=r"((r)[2]), "=r"((r)[3]) : "r"(a))

#define MMA16816(d, a, b0, b1) \
    asm volatile("mma.sync.aligned.m16n8k16.row.col.f32.bf16.bf16.f32 " \
        "{%0,%1,%2,%3}, {%4,%5,%6,%7}, {%8,%9}, {%0,%1,%2,%3};" \
        : "+f"((d)[0]), "+f"((d)[1]), "+f"((d)[2]), "+f"((d)[3]) \
        : "r"((a)[0]), "r"((a)[1]), "r"((a)[2]), "r"((a)[3]), "r"(b0), "r"(b1))

__device__ __forceinline__ uint32_t pk2(float a, float b) {
    __nv_bfloat162 t = __floats2bfloat162_rn(a, b);
    return *(uint32_t*)&t;
}

// ---------------- bf16x2 split: fp32 row[K] -> bf16 row[2K] ------------------
__global__ void split_bf16(const float* __restrict__ src,
                           __nv_bfloat16* __restrict__ dst,
                           int Kdim, size_t total) {
    size_t idx = (size_t)blockIdx.x * blockDim.x + threadIdx.x;
    if (idx >= total) return;
    int k = (int)(idx % Kdim);
    size_t r = idx / Kdim;
    float x = src[idx];
    __nv_bfloat16 hi = __float2bfloat16_rn(x);
    __nv_bfloat16 lo = __float2bfloat16_rn(x - __bfloat162float(hi));
    size_t o = r * (size_t)(2 * Kdim) + (size_t)(k >> 4) * 32 + (k & 15);
    dst[o] = hi;
    dst[o + 16] = lo;
}

// ---------------- bf16x2 mma.sync GEMM: C[M,N] = A[M,K] @ B[N,K]^T -----------
// K-chunk = 64 source k = 256 B/row (two 128-B swizzle halves). 2 stages.
// Stage: A 128x256B = 32KB, B 256x256B = 64KB  -> 96KB; x2 = 192KB smem.
#define GSTAGE 98304
#define GSMEM  (2*GSTAGE)

__global__ __launch_bounds__(512, 1)
void gemm_bf16x2(const __nv_bfloat16* __restrict__ Asp,
                 const __nv_bfloat16* __restrict__ Bsp,
                 float* __restrict__ C, int M, int N, int K) {
    extern __shared__ char smc[];
    const uint32_t sb = smem_u32(smc);
    const int tid = threadIdx.x, lane = tid & 31, wid = tid >> 5;
    const int bm = blockIdx.y * 128, bn = blockIdx.x * 256;
    const int wm = (wid & 3) * 32, wn = (wid >> 2) * 64;
    const size_t K2 = (size_t)2 * K;
    const int NCH = K / 64;

    float acc[2][8][4];
#pragma unroll
    for (int mt = 0; mt < 2; mt++)
#pragma unroll
        for (int nt = 0; nt < 8; nt++)
#pragma unroll
            for (int e = 0; e < 4; e++) acc[mt][nt][e] = 0.f;

    auto load = [&](int ch, int s) {
        const uint32_t sA = sb + s * GSTAGE;
        // A: 128 rows x 16 units (16B each); swizzle within each 128B half
#pragma unroll
        for (int i = 0; i < 4; i++) {
            int id = tid + i * 512, r = id >> 4, u = id & 15;
            cp16(sA + r * 256 + ((u >> 3) << 7) + (((u & 7) ^ (r & 7)) << 4),
                 Asp + (size_t)(bm + r) * K2 + ch * 128 + u * 8);
        }
        const uint32_t sB = sA + 32768;
#pragma unroll
        for (int i = 0; i < 8; i++) {
            int id = tid + i * 512, r = id >> 4, u = id & 15;
            cp16(sB + r * 256 + ((u >> 3) << 7) + (((u & 7) ^ (r & 7)) << 4),
                 Bsp + (size_t)(bn + r) * K2 + ch * 128 + u * 8);
        }
    };

    load(0, 0); CP_COMMIT();

    for (int i = 0; i < NCH; i++) {
        if (i + 1 < NCH) load(i + 1, (i + 1) & 1);
        CP_COMMIT();
        CP_WAIT(1);
        __syncthreads();

        const uint32_t sA = sb + (i & 1) * GSTAGE;
        const uint32_t sB = sA + 32768;
#pragma unroll
        for (int g = 0; g < 4; g++) {
            const int hof = (g >> 1) << 7;         // 128B half offset
            const int ub = (g & 1) * 4;            // unit base within half
            uint32_t Ah[2][4], Al[2][4];
#pragma unroll
            for (int mt = 0; mt < 2; mt++) {
                int row = wm + mt * 16 + (lane & 15);
                uint32_t base = sA + row * 256 + hof;
                int uh = ub + ((lane >> 4) & 1);
                LDSM4(Ah[mt], base + ((uh ^ (row & 7)) << 4));
                LDSM4(Al[mt], base + (((uh + 2) ^ (row & 7)) << 4));
            }
#pragma unroll
            for (int ntp = 0; ntp < 4; ntp++) {
                int nrow = wn + ntp * 16 + (lane & 7) + ((lane >> 4) & 1) * 8;
                uint32_t nbase = sB + nrow * 256 + hof;
                uint32_t Bh[4], Bl[4];
                int uk = ub + ((lane >> 3) & 1);
                LDSM4(Bh, nbase + ((uk ^ (nrow & 7)) << 4));
                LDSM4(Bl, nbase + (((uk + 2) ^ (nrow & 7)) << 4));
#pragma unroll
                for (int mt = 0; mt < 2; mt++)
#pragma unroll
                    for (int t = 0; t < 2; t++) {
                        float* d = acc[mt][ntp * 2 + t];
                        MMA16816(d, Ah[mt], Bh[2 * t], Bh[2 * t + 1]);
                        MMA16816(d, Ah[mt], Bl[2 * t], Bl[2 * t + 1]);
                        MMA16816(d, Al[mt], Bh[2 * t], Bh[2 * t + 1]);
                    }
            }
        }
        __syncthreads();
    }

#pragma unroll
    for (int mt = 0; mt < 2; mt++) {
        int r0 = bm + wm + mt * 16 + (lane >> 2);
#pragma unroll
        for (int nt = 0; nt < 8; nt++) {
            int c = bn + wn + nt * 8 + (lane & 3) * 2;
            float2 v0 = make_float2(acc[mt][nt][0], acc[mt][nt][1]);
            float2 v1 = make_float2(acc[mt][nt][2], acc[mt][nt][3]);
            *(float2*)&C[(size_t)r0 * N + c] = v0;
            *(float2*)&C[(size_t)(r0 + 8) * N + c] = v1;
        }
    }
}

// ---------------- fused rope + split + V-transpose ---------------------------
__global__ __launch_bounds__(256)
void convert_qkv(const float* __restrict__ rope) {
    __shared__ float vs[64][129];
    const int bh = blockIdx.y, b = bh >> 4, h = bh & 15;
    const int t0 = blockIdx.x * 64;
    const int tid = threadIdx.x;
    const int tl = tid >> 2, dbase = (tid & 3) * 32;
    const int t = t0 + tl;
    const float scale = 0.08838834764831845f;

    const float* qsrc = g_qkv + ((size_t)(b * Tt + t) * 3 + 0) * Dd + h * HD + dbase;
    const float* ksrc = qsrc + Dd;
    const float* vsrc = qsrc + 2 * Dd;
    __nv_bfloat16* qdst = g_qs + ((size_t)bh * Tt + t) * 256;
    __nv_bfloat16* kdst = g_ks + ((size_t)bh * Tt + t) * 256;

#pragma unroll
    for (int i = 0; i < 16; i++) {
        int d = dbase + 2 * i;
        float cr = rope[((size_t)t * 64 + (d >> 1)) * 2 + 0];
        float ci = rope[((size_t)t * 64 + (d >> 1)) * 2 + 1];
        int g = d >> 4, pos = d & 15;

        float xr = qsrc[2 * i], xi = qsrc[2 * i + 1];
        float ar = (xr * cr - xi * ci) * scale;
        float ai = (xi * cr + xr * ci) * scale;
        __nv_bfloat16 hr = __float2bfloat16_rn(ar), hi_ = __float2bfloat16_rn(ai);
        *(uint32_t*)&qdst[g * 32 + pos] = pk2(ar, ai);
        *(uint32_t*)&qdst[g * 32 + 16 + pos] =
            pk2(ar - __bfloat162float(hr), ai - __bfloat162float(hi_));

        float yr = ksrc[2 * i], yi = ksrc[2 * i + 1];
        float br = yr * cr - yi * ci;
        float bi = yi * cr + yr * ci;
        __nv_bfloat16 kr = __float2bfloat16_rn(br), ki = __float2bfloat16_rn(bi);
        *(uint32_t*)&kdst[g * 32 + pos] = pk2(br, bi);
        *(uint32_t*)&kdst[g * 32 + 16 + pos] =
            pk2(br - __bfloat162float(kr), bi - __bfloat162float(ki));

        vs[tl][d] = vsrc[2 * i];
        vs[tl][d + 1] = vsrc[2 * i + 1];
    }
    __syncthreads();

    const int dl = tid & 127, th = tid >> 7;
    __nv_bfloat16* vdst = g_vt + ((size_t)bh * 128 + dl) * 4096 + (t0 >> 4) * 32;
#pragma unroll
    for (int j = 0; j < 16; j++) {
        int tloc = th * 32 + 2 * j;
        float v0 = vs[tloc][dl], v1 = vs[tloc + 1][dl];
        int gt = tloc >> 4, pos = tloc & 15;
        __nv_bfloat16 h0 = __float2bfloat16_rn(v0), h1 = __float2bfloat16_rn(v1);
        *(uint32_t*)&vdst[gt * 32 + pos] = pk2(v0, v1);
        *(uint32_t*)&vdst[gt * 32 + 16 + pos] =
            pk2(v0 - __bfloat162float(h0), v1 - __bfloat162float(h1));
    }
}

// ---------------- bf16x2 mma flash attention ---------------------------------
// Heavy q-tiles scheduled FIRST (qt reversed) for wave balance.
#define ASQ 0
#define ASK 65536
#define ASV 131072
#define ASP 196608
#define ASMEM 229376

__global__ __launch_bounds__(256)
void attn_mma(float* __restrict__ out) {
    extern __shared__ char smc[];
    const uint32_t sb = smem_u32(smc);
    const int tid = threadIdx.x, lane = tid & 31, wid = tid >> 5;
    const int wm = wid & 3, wn = wid >> 2;
    const int qt = gridDim.x - 1 - blockIdx.x;     // heaviest first
    const int bh = blockIdx.y, b = bh >> 4, h = bh & 15;
    const int q0 = qt * 128;
    const int nkt = 2 * (qt + 1);

    const __nv_bfloat16* Qg = g_qs + ((size_t)bh * Tt + q0) * 256;
    const __nv_bfloat16* Kg = g_ks + (size_t)bh * Tt * 256;
    const __nv_bfloat16* Vg = g_vt + (size_t)bh * 128 * 4096;

    {
#pragma unroll
        for (int i = 0; i < 16; i++) {
            int id = tid + i * 256, r = id >> 5, u = id & 31;
            cp16(sb + ASQ + r * 512 + ((u ^ (r & 7)) << 4), Qg + (size_t)r * 256 + u * 8);
        }
#pragma unroll
        for (int i = 0; i < 8; i++) {
            int id = tid + i * 256, r = id >> 5, u = id & 31;
            cp16(sb + ASK + r * 512 + ((u ^ (r & 7)) << 4), Kg + (size_t)r * 256 + u * 8);
        }
#pragma unroll
        for (int i = 0; i < 8; i++) {
            int id = tid + i * 256, r = id >> 4, u = id & 15;
            cp16(sb + ASV + r * 256 + ((u ^ (r & 7)) << 4), Vg + (size_t)r * 4096 + u * 8);
        }
        CP_COMMIT();
    }

    float oacc[2][8][4];
#pragma unroll
    for (int mt = 0; mt < 2; mt++)
#pragma unroll
        for (int nt = 0; nt < 8; nt++)
#pragma unroll
            for (int e = 0; e < 4; e++) oacc[mt][nt][e] = 0.f;
    float lp[4] = {0.f, 0.f, 0.f, 0.f};

    for (int kt = 0; kt < nkt; kt++) {
        const int s = kt & 1;
        CP_WAIT(0);
        __syncthreads();

        if (kt + 1 < nkt) {
            const __nv_bfloat16* Kn = Kg + (size_t)(kt + 1) * 64 * 256;
            const uint32_t dk = sb + ASK + (s ^ 1) * 32768;
#pragma unroll
            for (int i = 0; i < 8; i++) {
                int id = tid + i * 256, r = id >> 5, u = id & 31;
                cp16(dk + r * 512 + ((u ^ (r & 7)) << 4), Kn + (size_t)r * 256 + u * 8);
            }
            const uint32_t dv = sb + ASV + (s ^ 1) * 32768;
#pragma unroll
            for (int i = 0; i < 8; i++) {
                int id = tid + i * 256, r = id >> 4, u = id & 15;
                cp16(dv + r * 256 + ((u ^ (r & 7)) << 4),
                     Vg + (size_t)r * 4096 + (kt + 1) * 128 + u * 8);
            }
            CP_COMMIT();
        }

        // ---- S = Q @ K^T ----
        float sacc[2][4][4];
#pragma unroll
        for (int mt = 0; mt < 2; mt++)
#pragma unroll
            for (int nt = 0; nt < 4; nt++)
#pragma unroll
                for (int e = 0; e < 4; e++) sacc[mt][nt][e] = 0.f;

        const uint32_t sq = sb + ASQ, sk = sb + ASK + s * 32768;
#pragma unroll
        for (int gd = 0; gd < 8; gd++) {
            uint32_t Ah[2][4], Al[2][4];
#pragma unroll
            for (int mt = 0; mt < 2; mt++) {
                int r = wm * 32 + mt * 16 + (lane & 15);
                int uh = gd * 4 + ((lane >> 4) & 1);
                LDSM4(Ah[mt], sq + r * 512 + ((uh ^ (r & 7)) << 4));
                LDSM4(Al[mt], sq + r * 512 + (((uh + 2) ^ (r & 7)) << 4));
            }
#pragma unroll
            for (int ntp = 0; ntp < 2; ntp++) {
                int nr = wn * 32 + ntp * 16 + (lane & 7) + ((lane >> 4) & 1) * 8;
                uint32_t Bh[4], Bl[4];
                int ukh = gd * 4 + ((lane >> 3) & 1);
                LDSM4(Bh, sk + nr * 512 + ((ukh ^ (nr & 7)) << 4));
                LDSM4(Bl, sk + nr * 512 + (((ukh + 2) ^ (nr & 7)) << 4));
#pragma unroll
                for (int mt = 0; mt < 2; mt++)
#pragma unroll
                    for (int t = 0; t < 2; t++) {
                        float* d = sacc[mt][ntp * 2 + t];
                        MMA16816(d, Ah[mt], Bh[2 * t], Bh[2 * t + 1]);
                        MMA16816(d, Ah[mt], Bl[2 * t], Bl[2 * t + 1]);
                        MMA16816(d, Al[mt], Bh[2 * t], Bh[2 * t + 1]);
                    }
            }
        }

        // ---- exp (no max) + causal mask + split-store P ----
        const bool edge = (kt >= nkt - 2);
#pragma unroll
        for (int mt = 0; mt < 2; mt++) {
            int r0 = wm * 32 + mt * 16 + (lane >> 2);
#pragma unroll
            for (int n8 = 0; n8 < 4; n8++) {
                int c0 = wn * 32 + n8 * 8 + (lane & 3) * 2;
                float e00 = __expf(sacc[mt][n8][0]);
                float e01 = __expf(sacc[mt][n8][1]);
                float e10 = __expf(sacc[mt][n8][2]);
                float e11 = __expf(sacc[mt][n8][3]);
                if (edge) {
                    int cg = kt * 64 + c0;
                    if (cg     > q0 + r0)     e00 = 0.f;
                    if (cg + 1 > q0 + r0)     e01 = 0.f;
                    if (cg     > q0 + r0 + 8) e10 = 0.f;
                    if (cg + 1 > q0 + r0 + 8) e11 = 0.f;
                }
                lp[mt * 2 + 0] += e00 + e01;
                lp[mt * 2 + 1] += e10 + e11;

                int g = c0 >> 4, pos = c0 & 15;
                int uh = g * 4 + (pos >> 3);
                int boff = (pos & 7) * 2;
                __nv_bfloat16 h00 = __float2bfloat16_rn(e00), h01 = __float2bfloat16_rn(e01);
                __nv_bfloat16 h10 = __float2bfloat16_rn(e10), h11 = __float2bfloat16_rn(e11);
                *(uint32_t*)(smc + ASP + r0 * 256 + ((uh ^ (r0 & 7)) << 4) + boff) = pk2(e00, e01);
                *(uint32_t*)(smc + ASP + r0 * 256 + (((uh + 2) ^ (r0 & 7)) << 4) + boff) =
                    pk2(e00 - __bfloat162float(h00), e01 - __bfloat162float(h01));
                int r1 = r0 + 8;
                *(uint32_t*)(smc + ASP + r1 * 256 + ((uh ^ (r1 & 7)) << 4) + boff) = pk2(e10, e11);
                *(uint32_t*)(smc + ASP + r1 * 256 + (((uh + 2) ^ (r1 & 7)) << 4) + boff) =
                    pk2(e10 - __bfloat162float(h10), e11 - __bfloat162float(h11));
            }
        }
        __syncthreads();

        // ---- O += P @ V^T ----
        const uint32_t sp = sb + ASP, sv = sb + ASV + s * 32768;
#pragma unroll
        for (int gt = 0; gt < 4; gt++) {
            uint32_t Ph[2][4], Pl[2][4];
#pragma unroll
            for (int mt = 0; mt < 2; mt++) {
                int r = wm * 32 + mt * 16 + (lane & 15);
                int uh = gt * 4 + ((lane >> 4) & 1);
                LDSM4(Ph[mt], sp + r * 256 + ((uh ^ (r & 7)) << 4));
                LDSM4(Pl[mt], sp + r * 256 + (((uh + 2) ^ (r & 7)) << 4));
            }
#pragma unroll
            for (int ntp = 0; ntp < 4; ntp++) {
                int nr = wn * 64 + ntp * 16 + (lane & 7) + ((lane >> 4) & 1) * 8;
                uint32_t Vh[4], Vl[4];
                int ukh = gt * 4 + ((lane >> 3) & 1);
                LDSM4(Vh, sv + nr * 256 + ((ukh ^ (nr & 7)) << 4));
                LDSM4(Vl, sv + nr * 256 + (((ukh + 2) ^ (nr & 7)) << 4));
#pragma unroll
                for (int mt = 0; mt < 2; mt++)
#pragma unroll
                    for (int t = 0; t < 2; t++) {
                        float* d = oacc[mt][ntp * 2 + t];
                        MMA16816(d, Ph[mt], Vh[2 * t], Vh[2 * t + 1]);
                        MMA16816(d, Ph[mt], Vl[2 * t], Vl[2 * t + 1]);
                        MMA16816(d, Pl[mt], Vh[2 * t], Vh[2 * t + 1]);
                    }
            }
        }
    }

    // ---- l reduce ----
#pragma unroll
    for (int sl = 0; sl < 4; sl++) {
        float v = lp[sl];
        v += __shfl_xor_sync(0xffffffffu, v, 1);
        v += __shfl_xor_sync(0xffffffffu, v, 2);
        lp[sl] = v;
    }
    __syncthreads();
    float* lred = (float*)(smc + ASP);
    if ((lane & 3) == 0) {
#pragma unroll
        for (int mt = 0; mt < 2; mt++)
#pragma unroll
            for (int rh = 0; rh < 2; rh++) {
                int r = wm * 32 + mt * 16 + rh * 8 + (lane >> 2);
                lred[r * 2 + wn] = lp[mt * 2 + rh];
            }
    }
    __syncthreads();

#pragma unroll
    for (int mt = 0; mt < 2; mt++)
#pragma unroll
        for (int rh = 0; rh < 2; rh++) {
            int r = wm * 32 + mt * 16 + rh * 8 + (lane >> 2);
            float inv = 1.0f / (lred[r * 2] + lred[r * 2 + 1]);
            size_t row = ((size_t)(b * Tt + q0 + r)) * Dd + h * HD;
#pragma unroll
            for (int n8 = 0; n8 < 8; n8++) {
                int c = wn * 64 + n8 * 8 + (lane & 3) * 2;
                float2 v = make_float2(oacc[mt][n8][rh * 2 + 0] * inv,
                                       oacc[mt][n8][rh * 2 + 1] * inv);
                *(float2*)&out[row + c] = v;
            }
        }
}

// ---------------- launcher --------------------------------------------------
extern "C" void kernel_launch(void* const* d_in, const int* in_sizes, int n_in,
                              void* d_out, int out_size) {
    (void)in_sizes; (void)n_in; (void)out_size;
    const float* x      = (const float*)d_in[0];
    const float* rope   = (const float*)d_in[1];
    const float* w_attn = (const float*)d_in[3];
    const float* w_proj = (const float*)d_in[4];
    float* out = (float*)d_out;

    float *qkv, *att;
    __nv_bfloat16 *xs, *as_, *ws1, *ws2;
    cudaGetSymbolAddress((void**)&qkv, g_qkv);
    cudaGetSymbolAddress((void**)&att, g_att);
    cudaGetSymbolAddress((void**)&xs,  g_xs);
    cudaGetSymbolAddress((void**)&as_, g_as);
    cudaGetSymbolAddress((void**)&ws1, g_ws1);
    cudaGetSymbolAddress((void**)&ws2, g_ws2);

    cudaFuncSetAttribute(gemm_bf16x2,
                         cudaFuncAttributeMaxDynamicSharedMemorySize, GSMEM);
    cudaFuncSetAttribute(attn_mma,
                         cudaFuncAttributeMaxDynamicSharedMemorySize, ASMEM);

    // splits
    {
        size_t n1 = (size_t)Bb * Tt * Dd;
        split_bf16<<<(unsigned)((n1 + 255) / 256), 256>>>(x, xs, Dd, n1);
        size_t n2 = (size_t)D3 * Dd;
        split_bf16<<<(unsigned)((n2 + 255) / 256), 256>>>(w_attn, ws1, Dd, n2);
        size_t n3 = (size_t)Dd * Dd;
        split_bf16<<<(unsigned)((n3 + 255) / 256), 256>>>(w_proj, ws2, Dd, n3);
    }

    // 1) QKV = X @ Wattn^T
    {
        dim3 grid(D3 / 256, (Bb * Tt) / 128);
        gemm_bf16x2<<<grid, 512, GSMEM>>>(xs, ws1, qkv, Bb * Tt, D3, Dd);
    }

    // 2) fused rope + split + V transpose
    {
        dim3 grid(Tt / 64, Bb * Hh);
        convert_qkv<<<grid, 256>>>(rope);
    }

    // 3) mma flash attention (heavy tiles first)
    {
        dim3 grid(Tt / 128, Bb * Hh);
        attn_mma<<<grid, 256, ASMEM>>>(att);
    }

    // 4) split att, out = att @ Wproj^T
    {
        size_t n4 = (size_t)Bb * Tt * Dd;
        split_bf16<<<(unsigned)((n4 + 255) / 256), 256>>>(att, as_, Dd, n4);
        dim3 grid(Dd / 256, (Bb * Tt) / 128);
        gemm_bf16x2<<<grid, 512, GSMEM>>>(as_, ws2, out, Bb * Tt, Dd, Dd);
    }
}

// round 7
// speedup vs baseline: 1.0329x; 1.0329x over previous
#include <cuda_runtime.h>
#include <cuda_bf16.h>
#include <cstdint>
#include <math.h>

#define Bb 2
#define Tt 2048
#define Dd 2048
#define Hh 16
#define HD 128
#define HD2 64
#define D3 (3*Dd)

// ---------------- scratch (static device globals) ----------------------------
__device__ float g_qkv[(size_t)Bb*Tt*D3];                 // [B,T,(q|k|v),D]
__device__ __nv_bfloat16 g_xs [(size_t)Bb*Tt*2*Dd];       // x split   [M, 2K]
__device__ __nv_bfloat16 g_as [(size_t)Bb*Tt*2*Dd];       // att split [M, 2K]
__device__ __nv_bfloat16 g_ws1[(size_t)D3*2*Dd];          // w_attn split [N, 2K]
__device__ __nv_bfloat16 g_ws2[(size_t)Dd*2*Dd];          // w_proj split [N, 2K]
__device__ __nv_bfloat16 g_qs [(size_t)Bb*Hh*Tt*2*HD];    // q roped+scaled split
__device__ __nv_bfloat16 g_ks [(size_t)Bb*Hh*Tt*2*HD];    // k roped split
__device__ __nv_bfloat16 g_vt [(size_t)Bb*Hh*HD*2*Tt];    // v^T split [b,h,d,4096]

// ---------------- PTX helpers ------------------------------------------------
__device__ __forceinline__ uint32_t smem_u32(const void* p) {
    uint32_t a;
    asm("{ .reg .u64 t; cvta.to.shared.u64 t, %1; cvt.u32.u64 %0, t; }"
        : "=r"(a) : "l"(p));
    return a;
}
__device__ __forceinline__ void cp16(uint32_t s, const void* g) {
    asm volatile("cp.async.cg.shared.global [%0], [%1], 16;" :: "r"(s), "l"(g));
}
#define CP_COMMIT() asm volatile("cp.async.commit_group;" ::: "memory")
#define CP_WAIT(n)  asm volatile("cp.async.wait_group %0;" :: "n"(n) : "memory")

#define LDSM4(r, a) \
    asm volatile("ldmatrix.sync.aligned.m8n8.x4.shared.b16 {%0,%1,%2,%3}, [%4];" \
        : "=r"((r)[0]), "=r"((r)[1]), "=r"((r)[2]), "=r"((r)[3]) : "r"(a))

#define MMA16816(d, a, b0, b1) \
    asm volatile("mma.sync.aligned.m16n8k16.row.col.f32.bf16.bf16.f32 " \
        "{%0,%1,%2,%3}, {%4,%5,%6,%7}, {%8,%9}, {%0,%1,%2,%3};" \
        : "+f"((d)[0]), "+f"((d)[1]), "+f"((d)[2]), "+f"((d)[3]) \
        : "r"((a)[0]), "r"((a)[1]), "r"((a)[2]), "r"((a)[3]), "r"(b0), "r"(b1))

__device__ __forceinline__ uint32_t pk2(float a, float b) {
    __nv_bfloat162 t = __floats2bfloat162_rn(a, b);
    return *(uint32_t*)&t;
}

// ---------------- bf16x2 split: fp32 row[K] -> bf16 row[2K] ------------------
__global__ void split_bf16(const float* __restrict__ src,
                           __nv_bfloat16* __restrict__ dst,
                           int Kdim, size_t total) {
    size_t idx = (size_t)blockIdx.x * blockDim.x + threadIdx.x;
    if (idx >= total) return;
    int k = (int)(idx % Kdim);
    size_t r = idx / Kdim;
    float x = src[idx];
    __nv_bfloat16 hi = __float2bfloat16_rn(x);
    __nv_bfloat16 lo = __float2bfloat16_rn(x - __bfloat162float(hi));
    size_t o = r * (size_t)(2 * Kdim) + (size_t)(k >> 4) * 32 + (k & 15);
    dst[o] = hi;
    dst[o + 16] = lo;
}

// ---------------- bf16x2 mma.sync GEMM: C[M,N] = A[M,K] @ B[N,K]^T -----------
// 128x128 tile, 256 threads (8 warps: wm 0-3 x 32 rows, wn 0-1 x 64 cols).
// K-chunk 32 source-k = 128B/row. 3 stages x 32KB = 96KB smem -> 2 CTAs/SM.
#define GSTAGE 32768
#define GSMEM  (3*GSTAGE)

__global__ __launch_bounds__(256, 2)
void gemm_bf16x2(const __nv_bfloat16* __restrict__ Asp,
                 const __nv_bfloat16* __restrict__ Bsp,
                 float* __restrict__ C, int M, int N, int K) {
    extern __shared__ char smc[];
    const uint32_t sb = smem_u32(smc);
    const int tid = threadIdx.x, lane = tid & 31, wid = tid >> 5;
    const int bm = blockIdx.y * 128, bn = blockIdx.x * 128;
    const int wm = (wid & 3) * 32, wn = (wid >> 2) * 64;
    const size_t K2 = (size_t)2 * K;
    const int NCH = K / 32;

    float acc[2][8][4];
#pragma unroll
    for (int mt = 0; mt < 2; mt++)
#pragma unroll
        for (int nt = 0; nt < 8; nt++)
#pragma unroll
            for (int e = 0; e < 4; e++) acc[mt][nt][e] = 0.f;

    auto load = [&](int ch, int s) {
        const uint32_t sA = sb + s * GSTAGE;
#pragma unroll
        for (int i = 0; i < 4; i++) {
            int id = tid + i * 256, r = id >> 3, u = id & 7;
            cp16(sA + r * 128 + ((u ^ (r & 7)) << 4),
                 Asp + (size_t)(bm + r) * K2 + ch * 64 + u * 8);
        }
        const uint32_t sB = sA + 16384;
#pragma unroll
        for (int i = 0; i < 4; i++) {
            int id = tid + i * 256, r = id >> 3, u = id & 7;
            cp16(sB + r * 128 + ((u ^ (r & 7)) << 4),
                 Bsp + (size_t)(bn + r) * K2 + ch * 64 + u * 8);
        }
    };

    load(0, 0); CP_COMMIT();
    load(1, 1); CP_COMMIT();

    for (int i = 0; i < NCH; i++) {
        if (i + 2 < NCH) load(i + 2, (i + 2) % 3);
        CP_COMMIT();
        CP_WAIT(2);
        __syncthreads();

        const uint32_t sA = sb + (i % 3) * GSTAGE;
        const uint32_t sB = sA + 16384;
#pragma unroll
        for (int sub = 0; sub < 2; sub++) {
            const int ubh = sub * 4, ubl = sub * 4 + 2;
            uint32_t Ah[2][4], Al[2][4];
#pragma unroll
            for (int mt = 0; mt < 2; mt++) {
                int row = wm + mt * 16 + (lane & 15);
                int uh = ubh + ((lane >> 4) & 1);
                LDSM4(Ah[mt], sA + row * 128 + ((uh ^ (row & 7)) << 4));
                int ul = ubl + ((lane >> 4) & 1);
                LDSM4(Al[mt], sA + row * 128 + ((ul ^ (row & 7)) << 4));
            }
#pragma unroll
            for (int ntp = 0; ntp < 4; ntp++) {
                int nrow = wn + ntp * 16 + (lane & 7) + ((lane >> 4) & 1) * 8;
                uint32_t Bh[4], Bl[4];
                int ukh = ubh + ((lane >> 3) & 1);
                LDSM4(Bh, sB + nrow * 128 + ((ukh ^ (nrow & 7)) << 4));
                int ukl = ubl + ((lane >> 3) & 1);
                LDSM4(Bl, sB + nrow * 128 + ((ukl ^ (nrow & 7)) << 4));
#pragma unroll
                for (int mt = 0; mt < 2; mt++)
#pragma unroll
                    for (int t = 0; t < 2; t++) {
                        float* d = acc[mt][ntp * 2 + t];
                        MMA16816(d, Ah[mt], Bh[2 * t], Bh[2 * t + 1]);
                        MMA16816(d, Ah[mt], Bl[2 * t], Bl[2 * t + 1]);
                        MMA16816(d, Al[mt], Bh[2 * t], Bh[2 * t + 1]);
                    }
            }
        }
        __syncthreads();
    }

#pragma unroll
    for (int mt = 0; mt < 2; mt++) {
        int r0 = bm + wm + mt * 16 + (lane >> 2);
#pragma unroll
        for (int nt = 0; nt < 8; nt++) {
            int c = bn + wn + nt * 8 + (lane & 3) * 2;
            float2 v0 = make_float2(acc[mt][nt][0], acc[mt][nt][1]);
            float2 v1 = make_float2(acc[mt][nt][2], acc[mt][nt][3]);
            *(float2*)&C[(size_t)r0 * N + c] = v0;
            *(float2*)&C[(size_t)(r0 + 8) * N + c] = v1;
        }
    }
}

// ---------------- fused rope + split + V-transpose ---------------------------
__global__ __launch_bounds__(256)
void convert_qkv(const float* __restrict__ rope) {
    __shared__ float vs[64][129];
    const int bh = blockIdx.y, b = bh >> 4, h = bh & 15;
    const int t0 = blockIdx.x * 64;
    const int tid = threadIdx.x;
    const int tl = tid >> 2, dbase = (tid & 3) * 32;
    const int t = t0 + tl;
    const float scale = 0.08838834764831845f;

    const float* qsrc = g_qkv + ((size_t)(b * Tt + t) * 3 + 0) * Dd + h * HD + dbase;
    const float* ksrc = qsrc + Dd;
    const float* vsrc = qsrc + 2 * Dd;
    __nv_bfloat16* qdst = g_qs + ((size_t)bh * Tt + t) * 256;
    __nv_bfloat16* kdst = g_ks + ((size_t)bh * Tt + t) * 256;

#pragma unroll
    for (int i = 0; i < 16; i++) {
        int d = dbase + 2 * i;
        float cr = rope[((size_t)t * 64 + (d >> 1)) * 2 + 0];
        float ci = rope[((size_t)t * 64 + (d >> 1)) * 2 + 1];
        int g = d >> 4, pos = d & 15;

        float xr = qsrc[2 * i], xi = qsrc[2 * i + 1];
        float ar = (xr * cr - xi * ci) * scale;
        float ai = (xi * cr + xr * ci) * scale;
        __nv_bfloat16 hr = __float2bfloat16_rn(ar), hi_ = __float2bfloat16_rn(ai);
        *(uint32_t*)&qdst[g * 32 + pos] = pk2(ar, ai);
        *(uint32_t*)&qdst[g * 32 + 16 + pos] =
            pk2(ar - __bfloat162float(hr), ai - __bfloat162float(hi_));

        float yr = ksrc[2 * i], yi = ksrc[2 * i + 1];
        float br = yr * cr - yi * ci;
        float bi = yi * cr + yr * ci;
        __nv_bfloat16 kr = __float2bfloat16_rn(br), ki = __float2bfloat16_rn(bi);
        *(uint32_t*)&kdst[g * 32 + pos] = pk2(br, bi);
        *(uint32_t*)&kdst[g * 32 + 16 + pos] =
            pk2(br - __bfloat162float(kr), bi - __bfloat162float(ki));

        vs[tl][d] = vsrc[2 * i];
        vs[tl][d + 1] = vsrc[2 * i + 1];
    }
    __syncthreads();

    const int dl = tid & 127, th = tid >> 7;
    __nv_bfloat16* vdst = g_vt + ((size_t)bh * 128 + dl) * 4096 + (t0 >> 4) * 32;
#pragma unroll
    for (int j = 0; j < 16; j++) {
        int tloc = th * 32 + 2 * j;
        float v0 = vs[tloc][dl], v1 = vs[tloc + 1][dl];
        int gt = tloc >> 4, pos = tloc & 15;
        __nv_bfloat16 h0 = __float2bfloat16_rn(v0), h1 = __float2bfloat16_rn(v1);
        *(uint32_t*)&vdst[gt * 32 + pos] = pk2(v0, v1);
        *(uint32_t*)&vdst[gt * 32 + 16 + pos] =
            pk2(v0 - __bfloat162float(h0), v1 - __bfloat162float(h1));
    }
}

// ---------------- bf16x2 mma flash attention ---------------------------------
// Heavy q-tiles first. Epilogue writes split-bf16 directly to g_as.
#define ASQ 0
#define ASK 65536
#define ASV 131072
#define ASP 196608
#define ASMEM 229376

__global__ __launch_bounds__(256)
void attn_mma(__nv_bfloat16* __restrict__ outs /* g_as */) {
    extern __shared__ char smc[];
    const uint32_t sb = smem_u32(smc);
    const int tid = threadIdx.x, lane = tid & 31, wid = tid >> 5;
    const int wm = wid & 3, wn = wid >> 2;
    const int qt = gridDim.x - 1 - blockIdx.x;
    const int bh = blockIdx.y, b = bh >> 4, h = bh & 15;
    const int q0 = qt * 128;
    const int nkt = 2 * (qt + 1);

    const __nv_bfloat16* Qg = g_qs + ((size_t)bh * Tt + q0) * 256;
    const __nv_bfloat16* Kg = g_ks + (size_t)bh * Tt * 256;
    const __nv_bfloat16* Vg = g_vt + (size_t)bh * 128 * 4096;

    {
#pragma unroll
        for (int i = 0; i < 16; i++) {
            int id = tid + i * 256, r = id >> 5, u = id & 31;
            cp16(sb + ASQ + r * 512 + ((u ^ (r & 7)) << 4), Qg + (size_t)r * 256 + u * 8);
        }
#pragma unroll
        for (int i = 0; i < 8; i++) {
            int id = tid + i * 256, r = id >> 5, u = id & 31;
            cp16(sb + ASK + r * 512 + ((u ^ (r & 7)) << 4), Kg + (size_t)r * 256 + u * 8);
        }
#pragma unroll
        for (int i = 0; i < 8; i++) {
            int id = tid + i * 256, r = id >> 4, u = id & 15;
            cp16(sb + ASV + r * 256 + ((u ^ (r & 7)) << 4), Vg + (size_t)r * 4096 + u * 8);
        }
        CP_COMMIT();
    }

    float oacc[2][8][4];
#pragma unroll
    for (int mt = 0; mt < 2; mt++)
#pragma unroll
        for (int nt = 0; nt < 8; nt++)
#pragma unroll
            for (int e = 0; e < 4; e++) oacc[mt][nt][e] = 0.f;
    float lp[4] = {0.f, 0.f, 0.f, 0.f};

    for (int kt = 0; kt < nkt; kt++) {
        const int s = kt & 1;
        CP_WAIT(0);
        __syncthreads();

        if (kt + 1 < nkt) {
            const __nv_bfloat16* Kn = Kg + (size_t)(kt + 1) * 64 * 256;
            const uint32_t dk = sb + ASK + (s ^ 1) * 32768;
#pragma unroll
            for (int i = 0; i < 8; i++) {
                int id = tid + i * 256, r = id >> 5, u = id & 31;
                cp16(dk + r * 512 + ((u ^ (r & 7)) << 4), Kn + (size_t)r * 256 + u * 8);
            }
            const uint32_t dv = sb + ASV + (s ^ 1) * 32768;
#pragma unroll
            for (int i = 0; i < 8; i++) {
                int id = tid + i * 256, r = id >> 4, u = id & 15;
                cp16(dv + r * 256 + ((u ^ (r & 7)) << 4),
                     Vg + (size_t)r * 4096 + (kt + 1) * 128 + u * 8);
            }
            CP_COMMIT();
        }

        // ---- S = Q @ K^T ----
        float sacc[2][4][4];
#pragma unroll
        for (int mt = 0; mt < 2; mt++)
#pragma unroll
            for (int nt = 0; nt < 4; nt++)
#pragma unroll
                for (int e = 0; e < 4; e++) sacc[mt][nt][e] = 0.f;

        const uint32_t sq = sb + ASQ, sk = sb + ASK + s * 32768;
#pragma unroll
        for (int gd = 0; gd < 8; gd++) {
            uint32_t Ah[2][4], Al[2][4];
#pragma unroll
            for (int mt = 0; mt < 2; mt++) {
                int r = wm * 32 + mt * 16 + (lane & 15);
                int uh = gd * 4 + ((lane >> 4) & 1);
                LDSM4(Ah[mt], sq + r * 512 + ((uh ^ (r & 7)) << 4));
                LDSM4(Al[mt], sq + r * 512 + (((uh + 2) ^ (r & 7)) << 4));
            }
#pragma unroll
            for (int ntp = 0; ntp < 2; ntp++) {
                int nr = wn * 32 + ntp * 16 + (lane & 7) + ((lane >> 4) & 1) * 8;
                uint32_t Bh[4], Bl[4];
                int ukh = gd * 4 + ((lane >> 3) & 1);
                LDSM4(Bh, sk + nr * 512 + ((ukh ^ (nr & 7)) << 4));
                LDSM4(Bl, sk + nr * 512 + (((ukh + 2) ^ (nr & 7)) << 4));
#pragma unroll
                for (int mt = 0; mt < 2; mt++)
#pragma unroll
                    for (int t = 0; t < 2; t++) {
                        float* d = sacc[mt][ntp * 2 + t];
                        MMA16816(d, Ah[mt], Bh[2 * t], Bh[2 * t + 1]);
                        MMA16816(d, Ah[mt], Bl[2 * t], Bl[2 * t + 1]);
                        MMA16816(d, Al[mt], Bh[2 * t], Bh[2 * t + 1]);
                    }
            }
        }

        // ---- exp + causal + split-store P ----
        const bool edge = (kt >= nkt - 2);
#pragma unroll
        for (int mt = 0; mt < 2; mt++) {
            int r0 = wm * 32 + mt * 16 + (lane >> 2);
#pragma unroll
            for (int n8 = 0; n8 < 4; n8++) {
                int c0 = wn * 32 + n8 * 8 + (lane & 3) * 2;
                float e00 = __expf(sacc[mt][n8][0]);
                float e01 = __expf(sacc[mt][n8][1]);
                float e10 = __expf(sacc[mt][n8][2]);
                float e11 = __expf(sacc[mt][n8][3]);
                if (edge) {
                    int cg = kt * 64 + c0;
                    if (cg     > q0 + r0)     e00 = 0.f;
                    if (cg + 1 > q0 + r0)     e01 = 0.f;
                    if (cg     > q0 + r0 + 8) e10 = 0.f;
                    if (cg + 1 > q0 + r0 + 8) e11 = 0.f;
                }
                lp[mt * 2 + 0] += e00 + e01;
                lp[mt * 2 + 1] += e10 + e11;

                int g = c0 >> 4, pos = c0 & 15;
                int uh = g * 4 + (pos >> 3);
                int boff = (pos & 7) * 2;
                __nv_bfloat16 h00 = __float2bfloat16_rn(e00), h01 = __float2bfloat16_rn(e01);
                __nv_bfloat16 h10 = __float2bfloat16_rn(e10), h11 = __float2bfloat16_rn(e11);
                *(uint32_t*)(smc + ASP + r0 * 256 + ((uh ^ (r0 & 7)) << 4) + boff) = pk2(e00, e01);
                *(uint32_t*)(smc + ASP + r0 * 256 + (((uh + 2) ^ (r0 & 7)) << 4) + boff) =
                    pk2(e00 - __bfloat162float(h00), e01 - __bfloat162float(h01));
                int r1 = r0 + 8;
                *(uint32_t*)(smc + ASP + r1 * 256 + ((uh ^ (r1 & 7)) << 4) + boff) = pk2(e10, e11);
                *(uint32_t*)(smc + ASP + r1 * 256 + (((uh + 2) ^ (r1 & 7)) << 4) + boff) =
                    pk2(e10 - __bfloat162float(h10), e11 - __bfloat162float(h11));
            }
        }
        __syncthreads();

        // ---- O += P @ V^T ----
        const uint32_t sp = sb + ASP, sv = sb + ASV + s * 32768;
#pragma unroll
        for (int gt = 0; gt < 4; gt++) {
            uint32_t Ph[2][4], Pl[2][4];
#pragma unroll
            for (int mt = 0; mt < 2; mt++) {
                int r = wm * 32 + mt * 16 + (lane & 15);
                int uh = gt * 4 + ((lane >> 4) & 1);
                LDSM4(Ph[mt], sp + r * 256 + ((uh ^ (r & 7)) << 4));
                LDSM4(Pl[mt], sp + r * 256 + (((uh + 2) ^ (r & 7)) << 4));
            }
#pragma unroll
            for (int ntp = 0; ntp < 4; ntp++) {
                int nr = wn * 64 + ntp * 16 + (lane & 7) + ((lane >> 4) & 1) * 8;
                uint32_t Vh[4], Vl[4];
                int ukh = gt * 4 + ((lane >> 3) & 1);
                LDSM4(Vh, sv + nr * 256 + ((ukh ^ (nr & 7)) << 4));
                LDSM4(Vl, sv + nr * 256 + (((ukh + 2) ^ (nr & 7)) << 4));
#pragma unroll
                for (int mt = 0; mt < 2; mt++)
#pragma unroll
                    for (int t = 0; t < 2; t++) {
                        float* d = oacc[mt][ntp * 2 + t];
                        MMA16816(d, Ph[mt], Vh[2 * t], Vh[2 * t + 1]);
                        MMA16816(d, Ph[mt], Vl[2 * t], Vl[2 * t + 1]);
                        MMA16816(d, Pl[mt], Vh[2 * t], Vh[2 * t + 1]);
                    }
            }
        }
    }

    // ---- l reduce ----
#pragma unroll
    for (int sl = 0; sl < 4; sl++) {
        float v = lp[sl];
        v += __shfl_xor_sync(0xffffffffu, v, 1);
        v += __shfl_xor_sync(0xffffffffu, v, 2);
        lp[sl] = v;
    }
    __syncthreads();
    float* lred = (float*)(smc + ASP);
    if ((lane & 3) == 0) {
#pragma unroll
        for (int mt = 0; mt < 2; mt++)
#pragma unroll
            for (int rh = 0; rh < 2; rh++) {
                int r = wm * 32 + mt * 16 + rh * 8 + (lane >> 2);
                lred[r * 2 + wn] = lp[mt * 2 + rh];
            }
    }
    __syncthreads();

    // ---- normalize + write split-bf16 directly to g_as ----
#pragma unroll
    for (int mt = 0; mt < 2; mt++)
#pragma unroll
        for (int rh = 0; rh < 2; rh++) {
            int r = wm * 32 + mt * 16 + rh * 8 + (lane >> 2);
            float inv = 1.0f / (lred[r * 2] + lred[r * 2 + 1]);
            __nv_bfloat16* dst = outs + (size_t)(b * Tt + q0 + r) * (2 * Dd);
#pragma unroll
            for (int n8 = 0; n8 < 8; n8++) {
                int c = wn * 64 + n8 * 8 + (lane & 3) * 2;   // 0..127 within head
                float o0 = oacc[mt][n8][rh * 2 + 0] * inv;
                float o1 = oacc[mt][n8][rh * 2 + 1] * inv;
                __nv_bfloat16 b0 = __float2bfloat16_rn(o0);
                __nv_bfloat16 b1 = __float2bfloat16_rn(o1);
                int gcol = h * 128 + c;
                size_t o = (size_t)(gcol >> 4) * 32 + (gcol & 15);
                *(uint32_t*)&dst[o] = pk2(o0, o1);
                *(uint32_t*)&dst[o + 16] =
                    pk2(o0 - __bfloat162float(b0), o1 - __bfloat162float(b1));
            }
        }
}

// ---------------- launcher --------------------------------------------------
extern "C" void kernel_launch(void* const* d_in, const int* in_sizes, int n_in,
                              void* d_out, int out_size) {
    (void)in_sizes; (void)n_in; (void)out_size;
    const float* x      = (const float*)d_in[0];
    const float* rope   = (const float*)d_in[1];
    const float* w_attn = (const float*)d_in[3];
    const float* w_proj = (const float*)d_in[4];
    float* out = (float*)d_out;

    float* qkv;
    __nv_bfloat16 *xs, *as_, *ws1, *ws2;
    cudaGetSymbolAddress((void**)&qkv, g_qkv);
    cudaGetSymbolAddress((void**)&xs,  g_xs);
    cudaGetSymbolAddress((void**)&as_, g_as);
    cudaGetSymbolAddress((void**)&ws1, g_ws1);
    cudaGetSymbolAddress((void**)&ws2, g_ws2);

    cudaFuncSetAttribute(gemm_bf16x2,
                         cudaFuncAttributeMaxDynamicSharedMemorySize, GSMEM);
    cudaFuncSetAttribute(attn_mma,
                         cudaFuncAttributeMaxDynamicSharedMemorySize, ASMEM);

    // splits
    {
        size_t n1 = (size_t)Bb * Tt * Dd;
        split_bf16<<<(unsigned)((n1 + 255) / 256), 256>>>(x, xs, Dd, n1);
        size_t n2 = (size_t)D3 * Dd;
        split_bf16<<<(unsigned)((n2 + 255) / 256), 256>>>(w_attn, ws1, Dd, n2);
        size_t n3 = (size_t)Dd * Dd;
        split_bf16<<<(unsigned)((n3 + 255) / 256), 256>>>(w_proj, ws2, Dd, n3);
    }

    // 1) QKV = X @ Wattn^T
    {
        dim3 grid(D3 / 128, (Bb * Tt) / 128);
        gemm_bf16x2<<<grid, 256, GSMEM>>>(xs, ws1, qkv, Bb * Tt, D3, Dd);
    }

    // 2) fused rope + split + V transpose
    {
        dim3 grid(Tt / 64, Bb * Hh);
        convert_qkv<<<grid, 256>>>(rope);
    }

    // 3) mma flash attention -> split output in g_as
    {
        dim3 grid(Tt / 128, Bb * Hh);
        attn_mma<<<grid, 256, ASMEM>>>(as_);
    }

    // 4) out = att @ Wproj^T
    {
        dim3 grid(Dd / 128, (Bb * Tt) / 128);
        gemm_bf16x2<<<grid, 256, GSMEM>>>(as_, ws2, out, Bb * Tt, Dd, Dd);
    }
}

// round 9
// speedup vs baseline: 1.1273x; 1.0913x over previous
#include <cuda_runtime.h>
#include <cuda_bf16.h>
#include <cuda_fp16.h>
#include <cstdint>
#include <math.h>

#define Bb 2
#define Tt 2048
#define Dd 2048
#define Hh 16
#define HD 128
#define HD2 64
#define D3 (3*Dd)

// ---------------- scratch (static device globals) ----------------------------
__device__ float g_qkv[(size_t)Bb*Tt*D3];                 // [B,T,(q|k|v),D]
__device__ __nv_bfloat16 g_xs [(size_t)Bb*Tt*2*Dd];       // x split   [M, 2K]
__device__ __nv_bfloat16 g_as [(size_t)Bb*Tt*2*Dd];       // att split [M, 2K]
__device__ __nv_bfloat16 g_ws1[(size_t)D3*2*Dd];          // w_attn split [N, 2K]
__device__ __nv_bfloat16 g_ws2[(size_t)Dd*2*Dd];          // w_proj split [N, 2K]
__device__ __nv_bfloat16 g_qs [(size_t)Bb*Hh*Tt*2*HD];    // q roped+scaled split
__device__ __nv_bfloat16 g_ks [(size_t)Bb*Hh*Tt*2*HD];    // k roped split
__device__ __half        g_vt [(size_t)Bb*Hh*HD*Tt];      // v^T fp16 [b,h,d,t]

// ---------------- PTX helpers ------------------------------------------------
__device__ __forceinline__ uint32_t smem_u32(const void* p) {
    uint32_t a;
    asm("{ .reg .u64 t; cvta.to.shared.u64 t, %1; cvt.u32.u64 %0, t; }"
        : "=r"(a) : "l"(p));
    return a;
}
__device__ __forceinline__ void cp16(uint32_t s, const void* g) {
    asm volatile("cp.async.cg.shared.global [%0], [%1], 16;" :: "r"(s), "l"(g));
}
#define CP_COMMIT() asm volatile("cp.async.commit_group;" ::: "memory")
#define CP_WAIT(n)  asm volatile("cp.async.wait_group %0;" :: "n"(n) : "memory")

#define LDSM4(r, a) \
    asm volatile("ldmatrix.sync.aligned.m8n8.x4.shared.b16 {%0,%1,%2,%3}, [%4];" \
        : "=r"((r)[0]), "=r"((r)[1]), "=r"((r)[2]), "=r"((r)[3]) : "r"(a))

#define MMA16816(d, a, b0, b1) \
    asm volatile("mma.sync.aligned.m16n8k16.row.col.f32.bf16.bf16.f32 " \
        "{%0,%1,%2,%3}, {%4,%5,%6,%7}, {%8,%9}, {%0,%1,%2,%3};" \
        : "+f"((d)[0]), "+f"((d)[1]), "+f"((d)[2]), "+f"((d)[3]) \
        : "r"((a)[0]), "r"((a)[1]), "r"((a)[2]), "r"((a)[3]), "r"(b0), "r"(b1))

#define MMA16816H(d, a, b0, b1) \
    asm volatile("mma.sync.aligned.m16n8k16.row.col.f32.f16.f16.f32 " \
        "{%0,%1,%2,%3}, {%4,%5,%6,%7}, {%8,%9}, {%0,%1,%2,%3};" \
        : "+f"((d)[0]), "+f"((d)[1]), "+f"((d)[2]), "+f"((d)[3]) \
        : "r"((a)[0]), "r"((a)[1]), "r"((a)[2]), "r"((a)[3]), "r"(b0), "r"(b1))

__device__ __forceinline__ uint32_t pk2(float a, float b) {
    __nv_bfloat162 t = __floats2bfloat162_rn(a, b);
    return *(uint32_t*)&t;
}
__device__ __forceinline__ uint32_t pk2h(float a, float b) {
    __half2 t = __floats2half2_rn(a, b);
    return *(uint32_t*)&t;
}

// ---------------- bf16x2 split: fp32 row[K] -> bf16 row[2K] ------------------
__global__ void split_bf16(const float* __restrict__ src,
                           __nv_bfloat16* __restrict__ dst,
                           int Kdim, size_t total) {
    size_t idx = (size_t)blockIdx.x * blockDim.x + threadIdx.x;
    if (idx >= total) return;
    int k = (int)(idx % Kdim);
    size_t r = idx / Kdim;
    float x = src[idx];
    __nv_bfloat16 hi = __float2bfloat16_rn(x);
    __nv_bfloat16 lo = __float2bfloat16_rn(x - __bfloat162float(hi));
    size_t o = r * (size_t)(2 * Kdim) + (size_t)(k >> 4) * 32 + (k & 15);
    dst[o] = hi;
    dst[o + 16] = lo;
}

// ---------------- bf16x2 mma.sync GEMM (unchanged) ---------------------------
#define GSTAGE 32768
#define GSMEM  (3*GSTAGE)

__global__ __launch_bounds__(256, 2)
void gemm_bf16x2(const __nv_bfloat16* __restrict__ Asp,
                 const __nv_bfloat16* __restrict__ Bsp,
                 float* __restrict__ C, int M, int N, int K) {
    extern __shared__ char smc[];
    const uint32_t sb = smem_u32(smc);
    const int tid = threadIdx.x, lane = tid & 31, wid = tid >> 5;
    const int bm = blockIdx.y * 128, bn = blockIdx.x * 128;
    const int wm = (wid & 3) * 32, wn = (wid >> 2) * 64;
    const size_t K2 = (size_t)2 * K;
    const int NCH = K / 32;

    float acc[2][8][4];
#pragma unroll
    for (int mt = 0; mt < 2; mt++)
#pragma unroll
        for (int nt = 0; nt < 8; nt++)
#pragma unroll
            for (int e = 0; e < 4; e++) acc[mt][nt][e] = 0.f;

    auto load = [&](int ch, int s) {
        const uint32_t sA = sb + s * GSTAGE;
#pragma unroll
        for (int i = 0; i < 4; i++) {
            int id = tid + i * 256, r = id >> 3, u = id & 7;
            cp16(sA + r * 128 + ((u ^ (r & 7)) << 4),
                 Asp + (size_t)(bm + r) * K2 + ch * 64 + u * 8);
        }
        const uint32_t sB = sA + 16384;
#pragma unroll
        for (int i = 0; i < 4; i++) {
            int id = tid + i * 256, r = id >> 3, u = id & 7;
            cp16(sB + r * 128 + ((u ^ (r & 7)) << 4),
                 Bsp + (size_t)(bn + r) * K2 + ch * 64 + u * 8);
        }
    };

    load(0, 0); CP_COMMIT();
    load(1, 1); CP_COMMIT();

    for (int i = 0; i < NCH; i++) {
        if (i + 2 < NCH) load(i + 2, (i + 2) % 3);
        CP_COMMIT();
        CP_WAIT(2);
        __syncthreads();

        const uint32_t sA = sb + (i % 3) * GSTAGE;
        const uint32_t sB = sA + 16384;
#pragma unroll
        for (int sub = 0; sub < 2; sub++) {
            const int ubh = sub * 4, ubl = sub * 4 + 2;
            uint32_t Ah[2][4], Al[2][4];
#pragma unroll
            for (int mt = 0; mt < 2; mt++) {
                int row = wm + mt * 16 + (lane & 15);
                int uh = ubh + ((lane >> 4) & 1);
                LDSM4(Ah[mt], sA + row * 128 + ((uh ^ (row & 7)) << 4));
                int ul = ubl + ((lane >> 4) & 1);
                LDSM4(Al[mt], sA + row * 128 + ((ul ^ (row & 7)) << 4));
            }
#pragma unroll
            for (int ntp = 0; ntp < 4; ntp++) {
                int nrow = wn + ntp * 16 + (lane & 7) + ((lane >> 4) & 1) * 8;
                uint32_t Bh[4], Bl[4];
                int ukh = ubh + ((lane >> 3) & 1);
                LDSM4(Bh, sB + nrow * 128 + ((ukh ^ (nrow & 7)) << 4));
                int ukl = ubl + ((lane >> 3) & 1);
                LDSM4(Bl, sB + nrow * 128 + ((ukl ^ (nrow & 7)) << 4));
#pragma unroll
                for (int mt = 0; mt < 2; mt++)
#pragma unroll
                    for (int t = 0; t < 2; t++) {
                        float* d = acc[mt][ntp * 2 + t];
                        MMA16816(d, Ah[mt], Bh[2 * t], Bh[2 * t + 1]);
                        MMA16816(d, Ah[mt], Bl[2 * t], Bl[2 * t + 1]);
                        MMA16816(d, Al[mt], Bh[2 * t], Bh[2 * t + 1]);
                    }
            }
        }
        __syncthreads();
    }

#pragma unroll
    for (int mt = 0; mt < 2; mt++) {
        int r0 = bm + wm + mt * 16 + (lane >> 2);
#pragma unroll
        for (int nt = 0; nt < 8; nt++) {
            int c = bn + wn + nt * 8 + (lane & 3) * 2;
            float2 v0 = make_float2(acc[mt][nt][0], acc[mt][nt][1]);
            float2 v1 = make_float2(acc[mt][nt][2], acc[mt][nt][3]);
            *(float2*)&C[(size_t)r0 * N + c] = v0;
            *(float2*)&C[(size_t)(r0 + 8) * N + c] = v1;
        }
    }
}

// ---------------- fused rope + split + V-transpose (V fp16) ------------------
__global__ __launch_bounds__(256)
void convert_qkv(const float* __restrict__ rope) {
    __shared__ float vs[64][129];
    const int bh = blockIdx.y, b = bh >> 4, h = bh & 15;
    const int t0 = blockIdx.x * 64;
    const int tid = threadIdx.x;
    const int tl = tid >> 2, dbase = (tid & 3) * 32;
    const int t = t0 + tl;
    const float scale = 0.08838834764831845f;

    const float* qsrc = g_qkv + ((size_t)(b * Tt + t) * 3 + 0) * Dd + h * HD + dbase;
    const float* ksrc = qsrc + Dd;
    const float* vsrc = qsrc + 2 * Dd;
    __nv_bfloat16* qdst = g_qs + ((size_t)bh * Tt + t) * 256;
    __nv_bfloat16* kdst = g_ks + ((size_t)bh * Tt + t) * 256;

#pragma unroll
    for (int i = 0; i < 16; i++) {
        int d = dbase + 2 * i;
        float cr = rope[((size_t)t * 64 + (d >> 1)) * 2 + 0];
        float ci = rope[((size_t)t * 64 + (d >> 1)) * 2 + 1];
        int g = d >> 4, pos = d & 15;

        float xr = qsrc[2 * i], xi = qsrc[2 * i + 1];
        float ar = (xr * cr - xi * ci) * scale;
        float ai = (xi * cr + xr * ci) * scale;
        __nv_bfloat16 hr = __float2bfloat16_rn(ar), hi_ = __float2bfloat16_rn(ai);
        *(uint32_t*)&qdst[g * 32 + pos] = pk2(ar, ai);
        *(uint32_t*)&qdst[g * 32 + 16 + pos] =
            pk2(ar - __bfloat162float(hr), ai - __bfloat162float(hi_));

        float yr = ksrc[2 * i], yi = ksrc[2 * i + 1];
        float br = yr * cr - yi * ci;
        float bi = yi * cr + yr * ci;
        __nv_bfloat16 kr = __float2bfloat16_rn(br), ki = __float2bfloat16_rn(bi);
        *(uint32_t*)&kdst[g * 32 + pos] = pk2(br, bi);
        *(uint32_t*)&kdst[g * 32 + 16 + pos] =
            pk2(br - __bfloat162float(kr), bi - __bfloat162float(ki));

        vs[tl][d] = vsrc[2 * i];
        vs[tl][d + 1] = vsrc[2 * i + 1];
    }
    __syncthreads();

    const int dl = tid & 127, th = tid >> 7;
    __half* vdst = g_vt + ((size_t)bh * 128 + dl) * Tt + t0;
#pragma unroll
    for (int j = 0; j < 16; j++) {
        int tloc = th * 32 + 2 * j;
        *(uint32_t*)&vdst[tloc] = pk2h(vs[tloc][dl], vs[tloc + 1][dl]);
    }
}

// ---------------- mma flash attention ----------------------------------------
// S = 3-product bf16 split QK^T;  PV = single-product fp16 P @ V.
// smem: Q 64K | K 2x32K | V 2x16K | P 16K = 176KB
#define ASQ 0
#define ASK 65536
#define ASV 131072
#define ASP 163840
#define ASMEM 180224

__global__ __launch_bounds__(256)
void attn_mma(__nv_bfloat16* __restrict__ outs /* g_as */) {
    extern __shared__ char smc[];
    const uint32_t sb = smem_u32(smc);
    const int tid = threadIdx.x, lane = tid & 31, wid = tid >> 5;
    const int wm = wid & 3, wn = wid >> 2;
    const int qt = gridDim.x - 1 - blockIdx.x;
    const int bh = blockIdx.y, b = bh >> 4, h = bh & 15;
    const int q0 = qt * 128;
    const int nkt = 2 * (qt + 1);

    const __nv_bfloat16* Qg = g_qs + ((size_t)bh * Tt + q0) * 256;
    const __nv_bfloat16* Kg = g_ks + (size_t)bh * Tt * 256;
    const __half* Vg = g_vt + (size_t)bh * 128 * Tt;

    {
#pragma unroll
        for (int i = 0; i < 16; i++) {
            int id = tid + i * 256, r = id >> 5, u = id & 31;
            cp16(sb + ASQ + r * 512 + ((u ^ (r & 7)) << 4), Qg + (size_t)r * 256 + u * 8);
        }
#pragma unroll
        for (int i = 0; i < 8; i++) {
            int id = tid + i * 256, r = id >> 5, u = id & 31;
            cp16(sb + ASK + r * 512 + ((u ^ (r & 7)) << 4), Kg + (size_t)r * 256 + u * 8);
        }
#pragma unroll
        for (int i = 0; i < 4; i++) {
            int id = tid + i * 256, r = id >> 3, u = id & 7;
            cp16(sb + ASV + r * 128 + ((u ^ (r & 7)) << 4), Vg + (size_t)r * Tt + u * 8);
        }
        CP_COMMIT();
    }

    float oacc[2][8][4];
#pragma unroll
    for (int mt = 0; mt < 2; mt++)
#pragma unroll
        for (int nt = 0; nt < 8; nt++)
#pragma unroll
            for (int e = 0; e < 4; e++) oacc[mt][nt][e] = 0.f;
    float lp[4] = {0.f, 0.f, 0.f, 0.f};

    for (int kt = 0; kt < nkt; kt++) {
        const int s = kt & 1;
        CP_WAIT(0);
        __syncthreads();

        if (kt + 1 < nkt) {
            const __nv_bfloat16* Kn = Kg + (size_t)(kt + 1) * 64 * 256;
            const uint32_t dk = sb + ASK + (s ^ 1) * 32768;
#pragma unroll
            for (int i = 0; i < 8; i++) {
                int id = tid + i * 256, r = id >> 5, u = id & 31;
                cp16(dk + r * 512 + ((u ^ (r & 7)) << 4), Kn + (size_t)r * 256 + u * 8);
            }
            const uint32_t dv = sb + ASV + (s ^ 1) * 16384;
#pragma unroll
            for (int i = 0; i < 4; i++) {
                int id = tid + i * 256, r = id >> 3, u = id & 7;
                cp16(dv + r * 128 + ((u ^ (r & 7)) << 4),
                     Vg + (size_t)r * Tt + (kt + 1) * 64 + u * 8);
            }
            CP_COMMIT();
        }

        // ---- S = Q @ K^T (3-product bf16 split) ----
        float sacc[2][4][4];
#pragma unroll
        for (int mt = 0; mt < 2; mt++)
#pragma unroll
            for (int nt = 0; nt < 4; nt++)
#pragma unroll
                for (int e = 0; e < 4; e++) sacc[mt][nt][e] = 0.f;

        const uint32_t sq = sb + ASQ, sk = sb + ASK + s * 32768;
#pragma unroll
        for (int gd = 0; gd < 8; gd++) {
            uint32_t Ah[2][4], Al[2][4];
#pragma unroll
            for (int mt = 0; mt < 2; mt++) {
                int r = wm * 32 + mt * 16 + (lane & 15);
                int uh = gd * 4 + ((lane >> 4) & 1);
                LDSM4(Ah[mt], sq + r * 512 + ((uh ^ (r & 7)) << 4));
                LDSM4(Al[mt], sq + r * 512 + (((uh + 2) ^ (r & 7)) << 4));
            }
#pragma unroll
            for (int ntp = 0; ntp < 2; ntp++) {
                int nr = wn * 32 + ntp * 16 + (lane & 7) + ((lane >> 4) & 1) * 8;
                uint32_t Bh[4], Bl[4];
                int ukh = gd * 4 + ((lane >> 3) & 1);
                LDSM4(Bh, sk + nr * 512 + ((ukh ^ (nr & 7)) << 4));
                LDSM4(Bl, sk + nr * 512 + (((ukh + 2) ^ (nr & 7)) << 4));
#pragma unroll
                for (int mt = 0; mt < 2; mt++)
#pragma unroll
                    for (int t = 0; t < 2; t++) {
                        float* d = sacc[mt][ntp * 2 + t];
                        MMA16816(d, Ah[mt], Bh[2 * t], Bh[2 * t + 1]);
                        MMA16816(d, Ah[mt], Bl[2 * t], Bl[2 * t + 1]);
                        MMA16816(d, Al[mt], Bh[2 * t], Bh[2 * t + 1]);
                    }
            }
        }

        // ---- exp + causal + store P (fp16, 128B rows) ----
        const bool edge = (kt >= nkt - 2);
#pragma unroll
        for (int mt = 0; mt < 2; mt++) {
            int r0 = wm * 32 + mt * 16 + (lane >> 2);
#pragma unroll
            for (int n8 = 0; n8 < 4; n8++) {
                int c0 = wn * 32 + n8 * 8 + (lane & 3) * 2;
                float e00 = __expf(sacc[mt][n8][0]);
                float e01 = __expf(sacc[mt][n8][1]);
                float e10 = __expf(sacc[mt][n8][2]);
                float e11 = __expf(sacc[mt][n8][3]);
                if (edge) {
                    int cg = kt * 64 + c0;
                    if (cg     > q0 + r0)     e00 = 0.f;
                    if (cg + 1 > q0 + r0)     e01 = 0.f;
                    if (cg     > q0 + r0 + 8) e10 = 0.f;
                    if (cg + 1 > q0 + r0 + 8) e11 = 0.f;
                }
                lp[mt * 2 + 0] += e00 + e01;
                lp[mt * 2 + 1] += e10 + e11;

                int uh = c0 >> 3;
                int boff = (c0 & 7) * 2;
                *(uint32_t*)(smc + ASP + r0 * 128 + ((uh ^ (r0 & 7)) << 4) + boff) = pk2h(e00, e01);
                int r1 = r0 + 8;
                *(uint32_t*)(smc + ASP + r1 * 128 + ((uh ^ (r1 & 7)) << 4) + boff) = pk2h(e10, e11);
            }
        }
        __syncthreads();

        // ---- O += P @ V^T (single fp16 product) ----
        const uint32_t sp = sb + ASP, sv = sb + ASV + s * 16384;
#pragma unroll
        for (int gt = 0; gt < 4; gt++) {
            uint32_t Ph[2][4];
#pragma unroll
            for (int mt = 0; mt < 2; mt++) {
                int r = wm * 32 + mt * 16 + (lane & 15);
                int uh = gt * 2 + ((lane >> 4) & 1);
                LDSM4(Ph[mt], sp + r * 128 + ((uh ^ (r & 7)) << 4));
            }
#pragma unroll
            for (int ntp = 0; ntp < 4; ntp++) {
                int nr = wn * 64 + ntp * 16 + (lane & 7) + ((lane >> 4) & 1) * 8;
                uint32_t Vh[4];
                int uk = gt * 2 + ((lane >> 3) & 1);
                LDSM4(Vh, sv + nr * 128 + ((uk ^ (nr & 7)) << 4));
#pragma unroll
                for (int mt = 0; mt < 2; mt++)
#pragma unroll
                    for (int t = 0; t < 2; t++)
                        MMA16816H(oacc[mt][ntp * 2 + t], Ph[mt], Vh[2 * t], Vh[2 * t + 1]);
            }
        }
    }

    // ---- l reduce ----
#pragma unroll
    for (int sl = 0; sl < 4; sl++) {
        float v = lp[sl];
        v += __shfl_xor_sync(0xffffffffu, v, 1);
        v += __shfl_xor_sync(0xffffffffu, v, 2);
        lp[sl] = v;
    }
    __syncthreads();
    float* lred = (float*)(smc + ASP);
    if ((lane & 3) == 0) {
#pragma unroll
        for (int mt = 0; mt < 2; mt++)
#pragma unroll
            for (int rh = 0; rh < 2; rh++) {
                int r = wm * 32 + mt * 16 + rh * 8 + (lane >> 2);
                lred[r * 2 + wn] = lp[mt * 2 + rh];
            }
    }
    __syncthreads();

    // ---- normalize + write split-bf16 directly to g_as ----
#pragma unroll
    for (int mt = 0; mt < 2; mt++)
#pragma unroll
        for (int rh = 0; rh < 2; rh++) {
            int r = wm * 32 + mt * 16 + rh * 8 + (lane >> 2);
            float inv = 1.0f / (lred[r * 2] + lred[r * 2 + 1]);
            __nv_bfloat16* dst = outs + (size_t)(b * Tt + q0 + r) * (2 * Dd);
#pragma unroll
            for (int n8 = 0; n8 < 8; n8++) {
                int c = wn * 64 + n8 * 8 + (lane & 3) * 2;
                float o0 = oacc[mt][n8][rh * 2 + 0] * inv;
                float o1 = oacc[mt][n8][rh * 2 + 1] * inv;
                __nv_bfloat16 b0 = __float2bfloat16_rn(o0);
                __nv_bfloat16 b1 = __float2bfloat16_rn(o1);
                int gcol = h * 128 + c;
                size_t o = (size_t)(gcol >> 4) * 32 + (gcol & 15);
                *(uint32_t*)&dst[o] = pk2(o0, o1);
                *(uint32_t*)&dst[o + 16] =
                    pk2(o0 - __bfloat162float(b0), o1 - __bfloat162float(b1));
            }
        }
}

// ---------------- launcher --------------------------------------------------
extern "C" void kernel_launch(void* const* d_in, const int* in_sizes, int n_in,
                              void* d_out, int out_size) {
    (void)in_sizes; (void)n_in; (void)out_size;
    const float* x      = (const float*)d_in[0];
    const float* rope   = (const float*)d_in[1];
    const float* w_attn = (const float*)d_in[3];
    const float* w_proj = (const float*)d_in[4];
    float* out = (float*)d_out;

    float* qkv;
    __nv_bfloat16 *xs, *as_, *ws1, *ws2;
    cudaGetSymbolAddress((void**)&qkv, g_qkv);
    cudaGetSymbolAddress((void**)&xs,  g_xs);
    cudaGetSymbolAddress((void**)&as_, g_as);
    cudaGetSymbolAddress((void**)&ws1, g_ws1);
    cudaGetSymbolAddress((void**)&ws2, g_ws2);

    cudaFuncSetAttribute(gemm_bf16x2,
                         cudaFuncAttributeMaxDynamicSharedMemorySize, GSMEM);
    cudaFuncSetAttribute(attn_mma,
                         cudaFuncAttributeMaxDynamicSharedMemorySize, ASMEM);

    // splits
    {
        size_t n1 = (size_t)Bb * Tt * Dd;
        split_bf16<<<(unsigned)((n1 + 255) / 256), 256>>>(x, xs, Dd, n1);
        size_t n2 = (size_t)D3 * Dd;
        split_bf16<<<(unsigned)((n2 + 255) / 256), 256>>>(w_attn, ws1, Dd, n2);
        size_t n3 = (size_t)Dd * Dd;
        split_bf16<<<(unsigned)((n3 + 255) / 256), 256>>>(w_proj, ws2, Dd, n3);
    }

    // 1) QKV = X @ Wattn^T
    {
        dim3 grid(D3 / 128, (Bb * Tt) / 128);
        gemm_bf16x2<<<grid, 256, GSMEM>>>(xs, ws1, qkv, Bb * Tt, D3, Dd);
    }

    // 2) fused rope + split + V transpose (V fp16)
    {
        dim3 grid(Tt / 64, Bb * Hh);
        convert_qkv<<<grid, 256>>>(rope);
    }

    // 3) mma flash attention -> split output in g_as
    {
        dim3 grid(Tt / 128, Bb * Hh);
        attn_mma<<<grid, 256, ASMEM>>>(as_);
    }

    // 4) out = att @ Wproj^T
    {
        dim3 grid(Dd / 128, (Bb * Tt) / 128);
        gemm_bf16x2<<<grid, 256, GSMEM>>>(as_, ws2, out, Bb * Tt, Dd, Dd);
    }
}

// round 10
// speedup vs baseline: 1.4067x; 1.2479x over previous
#include <cuda_runtime.h>
#include <cuda_bf16.h>
#include <cuda_fp16.h>
#include <cstdint>
#include <math.h>

#define Bb 2
#define Tt 2048
#define Dd 2048
#define Hh 16
#define HD 128
#define HD2 64
#define D3 (3*Dd)

// ---------------- scratch (static device globals) ----------------------------
__device__ float g_qkv[(size_t)Bb*Tt*D3];                 // [B,T,(q|k|v),D]
__device__ __half g_xs [(size_t)Bb*Tt*2*Dd];              // x split fp16 [M, 2K]
__device__ __half g_as [(size_t)Bb*Tt*2*Dd];              // att split fp16 [M, 2K]
__device__ __half g_ws1[(size_t)D3*2*Dd];                 // w_attn split fp16 [N, 2K]
__device__ __half g_ws2[(size_t)Dd*2*Dd];                 // w_proj split fp16 [N, 2K]
__device__ __nv_bfloat16 g_qs [(size_t)Bb*Hh*Tt*2*HD];    // q roped+scaled split bf16
__device__ __nv_bfloat16 g_ks [(size_t)Bb*Hh*Tt*2*HD];    // k roped split bf16
__device__ __half        g_vt [(size_t)Bb*Hh*HD*Tt];      // v^T fp16 [b,h,d,t]

// ---------------- PTX helpers ------------------------------------------------
__device__ __forceinline__ uint32_t smem_u32(const void* p) {
    uint32_t a;
    asm("{ .reg .u64 t; cvta.to.shared.u64 t, %1; cvt.u32.u64 %0, t; }"
        : "=r"(a) : "l"(p));
    return a;
}
__device__ __forceinline__ void cp16(uint32_t s, const void* g) {
    asm volatile("cp.async.cg.shared.global [%0], [%1], 16;" :: "r"(s), "l"(g));
}
#define CP_COMMIT() asm volatile("cp.async.commit_group;" ::: "memory")
#define CP_WAIT(n)  asm volatile("cp.async.wait_group %0;" :: "n"(n) : "memory")

#define LDSM4(r, a) \
    asm volatile("ldmatrix.sync.aligned.m8n8.x4.shared.b16 {%0,%1,%2,%3}, [%4];" \
        : "=r"((r)[0]), "=r"((r)[1]), "=r"((r)[2]), "=r"((r)[3]) : "r"(a))

#define MMA16816(d, a, b0, b1) \
    asm volatile("mma.sync.aligned.m16n8k16.row.col.f32.bf16.bf16.f32 " \
        "{%0,%1,%2,%3}, {%4,%5,%6,%7}, {%8,%9}, {%0,%1,%2,%3};" \
        : "+f"((d)[0]), "+f"((d)[1]), "+f"((d)[2]), "+f"((d)[3]) \
        : "r"((a)[0]), "r"((a)[1]), "r"((a)[2]), "r"((a)[3]), "r"(b0), "r"(b1))

#define MMA16816H(d, a, b0, b1) \
    asm volatile("mma.sync.aligned.m16n8k16.row.col.f32.f16.f16.f32 " \
        "{%0,%1,%2,%3}, {%4,%5,%6,%7}, {%8,%9}, {%0,%1,%2,%3};" \
        : "+f"((d)[0]), "+f"((d)[1]), "+f"((d)[2]), "+f"((d)[3]) \
        : "r"((a)[0]), "r"((a)[1]), "r"((a)[2]), "r"((a)[3]), "r"(b0), "r"(b1))

__device__ __forceinline__ uint32_t pk2(float a, float b) {
    __nv_bfloat162 t = __floats2bfloat162_rn(a, b);
    return *(uint32_t*)&t;
}
__device__ __forceinline__ uint32_t pk2h(float a, float b) {
    __half2 t = __floats2half2_rn(a, b);
    return *(uint32_t*)&t;
}

// ---------------- fp16x2 split: fp32 row[K] -> fp16 row[2K] ------------------
__global__ void split_fp16(const float* __restrict__ src,
                           __half* __restrict__ dst,
                           int Kdim, size_t total) {
    size_t idx = (size_t)blockIdx.x * blockDim.x + threadIdx.x;
    if (idx >= total) return;
    int k = (int)(idx % Kdim);
    size_t r = idx / Kdim;
    float x = src[idx];
    __half hi = __float2half_rn(x);
    __half lo = __float2half_rn(x - __half2float(hi));
    size_t o = r * (size_t)(2 * Kdim) + (size_t)(k >> 4) * 32 + (k & 15);
    dst[o] = hi;
    dst[o + 16] = lo;
}

// ---------------- fp16 2-product mma.sync GEMM -------------------------------
// C = A @ B^T: A split (hi+lo) fp16, B hi-only (lo stored but unread).
#define GSTAGE 32768
#define GSMEM  (3*GSTAGE)

__global__ __launch_bounds__(256, 2)
void gemm_fp16x2(const __half* __restrict__ Asp,
                 const __half* __restrict__ Bsp,
                 float* __restrict__ C, int M, int N, int K) {
    extern __shared__ char smc[];
    const uint32_t sb = smem_u32(smc);
    const int tid = threadIdx.x, lane = tid & 31, wid = tid >> 5;
    const int bm = blockIdx.y * 128, bn = blockIdx.x * 128;
    const int wm = (wid & 3) * 32, wn = (wid >> 2) * 64;
    const size_t K2 = (size_t)2 * K;
    const int NCH = K / 32;

    float acc[2][8][4];
#pragma unroll
    for (int mt = 0; mt < 2; mt++)
#pragma unroll
        for (int nt = 0; nt < 8; nt++)
#pragma unroll
            for (int e = 0; e < 4; e++) acc[mt][nt][e] = 0.f;

    auto load = [&](int ch, int s) {
        const uint32_t sA = sb + s * GSTAGE;
#pragma unroll
        for (int i = 0; i < 4; i++) {
            int id = tid + i * 256, r = id >> 3, u = id & 7;
            cp16(sA + r * 128 + ((u ^ (r & 7)) << 4),
                 Asp + (size_t)(bm + r) * K2 + ch * 64 + u * 8);
        }
        const uint32_t sB = sA + 16384;
#pragma unroll
        for (int i = 0; i < 4; i++) {
            int id = tid + i * 256, r = id >> 3, u = id & 7;
            cp16(sB + r * 128 + ((u ^ (r & 7)) << 4),
                 Bsp + (size_t)(bn + r) * K2 + ch * 64 + u * 8);
        }
    };

    load(0, 0); CP_COMMIT();
    load(1, 1); CP_COMMIT();

    for (int i = 0; i < NCH; i++) {
        if (i + 2 < NCH) load(i + 2, (i + 2) % 3);
        CP_COMMIT();
        CP_WAIT(2);
        __syncthreads();

        const uint32_t sA = sb + (i % 3) * GSTAGE;
        const uint32_t sB = sA + 16384;
#pragma unroll
        for (int sub = 0; sub < 2; sub++) {
            const int ubh = sub * 4, ubl = sub * 4 + 2;
            uint32_t Ah[2][4], Al[2][4];
#pragma unroll
            for (int mt = 0; mt < 2; mt++) {
                int row = wm + mt * 16 + (lane & 15);
                int uh = ubh + ((lane >> 4) & 1);
                LDSM4(Ah[mt], sA + row * 128 + ((uh ^ (row & 7)) << 4));
                int ul = ubl + ((lane >> 4) & 1);
                LDSM4(Al[mt], sA + row * 128 + ((ul ^ (row & 7)) << 4));
            }
#pragma unroll
            for (int ntp = 0; ntp < 4; ntp++) {
                int nrow = wn + ntp * 16 + (lane & 7) + ((lane >> 4) & 1) * 8;
                uint32_t Bh[4];
                int ukh = ubh + ((lane >> 3) & 1);
                LDSM4(Bh, sB + nrow * 128 + ((ukh ^ (nrow & 7)) << 4));
#pragma unroll
                for (int mt = 0; mt < 2; mt++)
#pragma unroll
                    for (int t = 0; t < 2; t++) {
                        float* d = acc[mt][ntp * 2 + t];
                        MMA16816H(d, Ah[mt], Bh[2 * t], Bh[2 * t + 1]);
                        MMA16816H(d, Al[mt], Bh[2 * t], Bh[2 * t + 1]);
                    }
            }
        }
        __syncthreads();
    }

#pragma unroll
    for (int mt = 0; mt < 2; mt++) {
        int r0 = bm + wm + mt * 16 + (lane >> 2);
#pragma unroll
        for (int nt = 0; nt < 8; nt++) {
            int c = bn + wn + nt * 8 + (lane & 3) * 2;
            float2 v0 = make_float2(acc[mt][nt][0], acc[mt][nt][1]);
            float2 v1 = make_float2(acc[mt][nt][2], acc[mt][nt][3]);
            *(float2*)&C[(size_t)r0 * N + c] = v0;
            *(float2*)&C[(size_t)(r0 + 8) * N + c] = v1;
        }
    }
}

// ---------------- fused rope + split + V-transpose (V fp16) ------------------
__global__ __launch_bounds__(256)
void convert_qkv(const float* __restrict__ rope) {
    __shared__ float vs[64][129];
    const int bh = blockIdx.y, b = bh >> 4, h = bh & 15;
    const int t0 = blockIdx.x * 64;
    const int tid = threadIdx.x;
    const int tl = tid >> 2, dbase = (tid & 3) * 32;
    const int t = t0 + tl;
    const float scale = 0.08838834764831845f;

    const float* qsrc = g_qkv + ((size_t)(b * Tt + t) * 3 + 0) * Dd + h * HD + dbase;
    const float* ksrc = qsrc + Dd;
    const float* vsrc = qsrc + 2 * Dd;
    __nv_bfloat16* qdst = g_qs + ((size_t)bh * Tt + t) * 256;
    __nv_bfloat16* kdst = g_ks + ((size_t)bh * Tt + t) * 256;

#pragma unroll
    for (int i = 0; i < 16; i++) {
        int d = dbase + 2 * i;
        float cr = rope[((size_t)t * 64 + (d >> 1)) * 2 + 0];
        float ci = rope[((size_t)t * 64 + (d >> 1)) * 2 + 1];
        int g = d >> 4, pos = d & 15;

        float xr = qsrc[2 * i], xi = qsrc[2 * i + 1];
        float ar = (xr * cr - xi * ci) * scale;
        float ai = (xi * cr + xr * ci) * scale;
        __nv_bfloat16 hr = __float2bfloat16_rn(ar), hi_ = __float2bfloat16_rn(ai);
        *(uint32_t*)&qdst[g * 32 + pos] = pk2(ar, ai);
        *(uint32_t*)&qdst[g * 32 + 16 + pos] =
            pk2(ar - __bfloat162float(hr), ai - __bfloat162float(hi_));

        float yr = ksrc[2 * i], yi = ksrc[2 * i + 1];
        float br = yr * cr - yi * ci;
        float bi = yi * cr + yr * ci;
        __nv_bfloat16 kr = __float2bfloat16_rn(br), ki = __float2bfloat16_rn(bi);
        *(uint32_t*)&kdst[g * 32 + pos] = pk2(br, bi);
        *(uint32_t*)&kdst[g * 32 + 16 + pos] =
            pk2(br - __bfloat162float(kr), bi - __bfloat162float(ki));

        vs[tl][d] = vsrc[2 * i];
        vs[tl][d + 1] = vsrc[2 * i + 1];
    }
    __syncthreads();

    const int dl = tid & 127, th = tid >> 7;
    __half* vdst = g_vt + ((size_t)bh * 128 + dl) * Tt + t0;
#pragma unroll
    for (int j = 0; j < 16; j++) {
        int tloc = th * 32 + 2 * j;
        *(uint32_t*)&vdst[tloc] = pk2h(vs[tloc][dl], vs[tloc + 1][dl]);
    }
}

// ---------------- mma flash attention ----------------------------------------
// S = 3-product bf16 split QK^T;  PV = single fp16 product.
// smem: Q 64K | K 2x32K | V 2x16K | P 16K = 176KB
#define ASQ 0
#define ASK 65536
#define ASV 131072
#define ASP 163840
#define ASMEM 180224

__global__ __launch_bounds__(256)
void attn_mma(__half* __restrict__ outs /* g_as */) {
    extern __shared__ char smc[];
    const uint32_t sb = smem_u32(smc);
    const int tid = threadIdx.x, lane = tid & 31, wid = tid >> 5;
    const int wm = wid & 3, wn = wid >> 2;
    const int qt = gridDim.x - 1 - blockIdx.x;
    const int bh = blockIdx.y, b = bh >> 4, h = bh & 15;
    const int q0 = qt * 128;
    const int nkt = 2 * (qt + 1);

    const __nv_bfloat16* Qg = g_qs + ((size_t)bh * Tt + q0) * 256;
    const __nv_bfloat16* Kg = g_ks + (size_t)bh * Tt * 256;
    const __half* Vg = g_vt + (size_t)bh * 128 * Tt;

    {
#pragma unroll
        for (int i = 0; i < 16; i++) {
            int id = tid + i * 256, r = id >> 5, u = id & 31;
            cp16(sb + ASQ + r * 512 + ((u ^ (r & 7)) << 4), Qg + (size_t)r * 256 + u * 8);
        }
#pragma unroll
        for (int i = 0; i < 8; i++) {
            int id = tid + i * 256, r = id >> 5, u = id & 31;
            cp16(sb + ASK + r * 512 + ((u ^ (r & 7)) << 4), Kg + (size_t)r * 256 + u * 8);
        }
#pragma unroll
        for (int i = 0; i < 4; i++) {
            int id = tid + i * 256, r = id >> 3, u = id & 7;
            cp16(sb + ASV + r * 128 + ((u ^ (r & 7)) << 4), Vg + (size_t)r * Tt + u * 8);
        }
        CP_COMMIT();
    }

    float oacc[2][8][4];
#pragma unroll
    for (int mt = 0; mt < 2; mt++)
#pragma unroll
        for (int nt = 0; nt < 8; nt++)
#pragma unroll
            for (int e = 0; e < 4; e++) oacc[mt][nt][e] = 0.f;
    float lp[4] = {0.f, 0.f, 0.f, 0.f};

    for (int kt = 0; kt < nkt; kt++) {
        const int s = kt & 1;
        CP_WAIT(0);
        __syncthreads();

        if (kt + 1 < nkt) {
            const __nv_bfloat16* Kn = Kg + (size_t)(kt + 1) * 64 * 256;
            const uint32_t dk = sb + ASK + (s ^ 1) * 32768;
#pragma unroll
            for (int i = 0; i < 8; i++) {
                int id = tid + i * 256, r = id >> 5, u = id & 31;
                cp16(dk + r * 512 + ((u ^ (r & 7)) << 4), Kn + (size_t)r * 256 + u * 8);
            }
            const uint32_t dv = sb + ASV + (s ^ 1) * 16384;
#pragma unroll
            for (int i = 0; i < 4; i++) {
                int id = tid + i * 256, r = id >> 3, u = id & 7;
                cp16(dv + r * 128 + ((u ^ (r & 7)) << 4),
                     Vg + (size_t)r * Tt + (kt + 1) * 64 + u * 8);
            }
            CP_COMMIT();
        }

        // ---- S = Q @ K^T (3-product bf16 split) ----
        float sacc[2][4][4];
#pragma unroll
        for (int mt = 0; mt < 2; mt++)
#pragma unroll
            for (int nt = 0; nt < 4; nt++)
#pragma unroll
                for (int e = 0; e < 4; e++) sacc[mt][nt][e] = 0.f;

        const uint32_t sq = sb + ASQ, sk = sb + ASK + s * 32768;
#pragma unroll
        for (int gd = 0; gd < 8; gd++) {
            uint32_t Ah[2][4], Al[2][4];
#pragma unroll
            for (int mt = 0; mt < 2; mt++) {
                int r = wm * 32 + mt * 16 + (lane & 15);
                int uh = gd * 4 + ((lane >> 4) & 1);
                LDSM4(Ah[mt], sq + r * 512 + ((uh ^ (r & 7)) << 4));
                LDSM4(Al[mt], sq + r * 512 + (((uh + 2) ^ (r & 7)) << 4));
            }
#pragma unroll
            for (int ntp = 0; ntp < 2; ntp++) {
                int nr = wn * 32 + ntp * 16 + (lane & 7) + ((lane >> 4) & 1) * 8;
                uint32_t Bh[4], Bl[4];
                int ukh = gd * 4 + ((lane >> 3) & 1);
                LDSM4(Bh, sk + nr * 512 + ((ukh ^ (nr & 7)) << 4));
                LDSM4(Bl, sk + nr * 512 + (((ukh + 2) ^ (nr & 7)) << 4));
#pragma unroll
                for (int mt = 0; mt < 2; mt++)
#pragma unroll
                    for (int t = 0; t < 2; t++) {
                        float* d = sacc[mt][ntp * 2 + t];
                        MMA16816(d, Ah[mt], Bh[2 * t], Bh[2 * t + 1]);
                        MMA16816(d, Ah[mt], Bl[2 * t], Bl[2 * t + 1]);
                        MMA16816(d, Al[mt], Bh[2 * t], Bh[2 * t + 1]);
                    }
            }
        }

        // ---- exp + causal + store P (fp16) ----
        const bool edge = (kt >= nkt - 2);
#pragma unroll
        for (int mt = 0; mt < 2; mt++) {
            int r0 = wm * 32 + mt * 16 + (lane >> 2);
#pragma unroll
            for (int n8 = 0; n8 < 4; n8++) {
                int c0 = wn * 32 + n8 * 8 + (lane & 3) * 2;
                float e00 = __expf(sacc[mt][n8][0]);
                float e01 = __expf(sacc[mt][n8][1]);
                float e10 = __expf(sacc[mt][n8][2]);
                float e11 = __expf(sacc[mt][n8][3]);
                if (edge) {
                    int cg = kt * 64 + c0;
                    if (cg     > q0 + r0)     e00 = 0.f;
                    if (cg + 1 > q0 + r0)     e01 = 0.f;
                    if (cg     > q0 + r0 + 8) e10 = 0.f;
                    if (cg + 1 > q0 + r0 + 8) e11 = 0.f;
                }
                lp[mt * 2 + 0] += e00 + e01;
                lp[mt * 2 + 1] += e10 + e11;

                int uh = c0 >> 3;
                int boff = (c0 & 7) * 2;
                *(uint32_t*)(smc + ASP + r0 * 128 + ((uh ^ (r0 & 7)) << 4) + boff) = pk2h(e00, e01);
                int r1 = r0 + 8;
                *(uint32_t*)(smc + ASP + r1 * 128 + ((uh ^ (r1 & 7)) << 4) + boff) = pk2h(e10, e11);
            }
        }
        __syncthreads();

        // ---- O += P @ V^T (single fp16 product) ----
        const uint32_t sp = sb + ASP, sv = sb + ASV + s * 16384;
#pragma unroll
        for (int gt = 0; gt < 4; gt++) {
            uint32_t Ph[2][4];
#pragma unroll
            for (int mt = 0; mt < 2; mt++) {
                int r = wm * 32 + mt * 16 + (lane & 15);
                int uh = gt * 2 + ((lane >> 4) & 1);
                LDSM4(Ph[mt], sp + r * 128 + ((uh ^ (r & 7)) << 4));
            }
#pragma unroll
            for (int ntp = 0; ntp < 4; ntp++) {
                int nr = wn * 64 + ntp * 16 + (lane & 7) + ((lane >> 4) & 1) * 8;
                uint32_t Vh[4];
                int uk = gt * 2 + ((lane >> 3) & 1);
                LDSM4(Vh, sv + nr * 128 + ((uk ^ (nr & 7)) << 4));
#pragma unroll
                for (int mt = 0; mt < 2; mt++)
#pragma unroll
                    for (int t = 0; t < 2; t++)
                        MMA16816H(oacc[mt][ntp * 2 + t], Ph[mt], Vh[2 * t], Vh[2 * t + 1]);
            }
        }
    }

    // ---- l reduce ----
#pragma unroll
    for (int sl = 0; sl < 4; sl++) {
        float v = lp[sl];
        v += __shfl_xor_sync(0xffffffffu, v, 1);
        v += __shfl_xor_sync(0xffffffffu, v, 2);
        lp[sl] = v;
    }
    __syncthreads();
    float* lred = (float*)(smc + ASP);
    if ((lane & 3) == 0) {
#pragma unroll
        for (int mt = 0; mt < 2; mt++)
#pragma unroll
            for (int rh = 0; rh < 2; rh++) {
                int r = wm * 32 + mt * 16 + rh * 8 + (lane >> 2);
                lred[r * 2 + wn] = lp[mt * 2 + rh];
            }
    }
    __syncthreads();

    // ---- normalize + write split-fp16 directly to g_as ----
#pragma unroll
    for (int mt = 0; mt < 2; mt++)
#pragma unroll
        for (int rh = 0; rh < 2; rh++) {
            int r = wm * 32 + mt * 16 + rh * 8 + (lane >> 2);
            float inv = 1.0f / (lred[r * 2] + lred[r * 2 + 1]);
            __half* dst = outs + (size_t)(b * Tt + q0 + r) * (2 * Dd);
#pragma unroll
            for (int n8 = 0; n8 < 8; n8++) {
                int c = wn * 64 + n8 * 8 + (lane & 3) * 2;
                float o0 = oacc[mt][n8][rh * 2 + 0] * inv;
                float o1 = oacc[mt][n8][rh * 2 + 1] * inv;
                __half b0 = __float2half_rn(o0);
                __half b1 = __float2half_rn(o1);
                int gcol = h * 128 + c;
                size_t o = (size_t)(gcol >> 4) * 32 + (gcol & 15);
                *(uint32_t*)&dst[o] = pk2h(o0, o1);
                *(uint32_t*)&dst[o + 16] =
                    pk2h(o0 - __half2float(b0), o1 - __half2float(b1));
            }
        }
}

// ---------------- launcher --------------------------------------------------
extern "C" void kernel_launch(void* const* d_in, const int* in_sizes, int n_in,
                              void* d_out, int out_size) {
    (void)in_sizes; (void)n_in; (void)out_size;
    const float* x      = (const float*)d_in[0];
    const float* rope   = (const float*)d_in[1];
    const float* w_attn = (const float*)d_in[3];
    const float* w_proj = (const float*)d_in[4];
    float* out = (float*)d_out;

    float* qkv;
    __half *xs, *as_, *ws1, *ws2;
    cudaGetSymbolAddress((void**)&qkv, g_qkv);
    cudaGetSymbolAddress((void**)&xs,  g_xs);
    cudaGetSymbolAddress((void**)&as_, g_as);
    cudaGetSymbolAddress((void**)&ws1, g_ws1);
    cudaGetSymbolAddress((void**)&ws2, g_ws2);

    cudaFuncSetAttribute(gemm_fp16x2,
                         cudaFuncAttributeMaxDynamicSharedMemorySize, GSMEM);
    cudaFuncSetAttribute(attn_mma,
                         cudaFuncAttributeMaxDynamicSharedMemorySize, ASMEM);

    // splits
    {
        size_t n1 = (size_t)Bb * Tt * Dd;
        split_fp16<<<(unsigned)((n1 + 255) / 256), 256>>>(x, xs, Dd, n1);
        size_t n2 = (size_t)D3 * Dd;
        split_fp16<<<(unsigned)((n2 + 255) / 256), 256>>>(w_attn, ws1, Dd, n2);
        size_t n3 = (size_t)Dd * Dd;
        split_fp16<<<(unsigned)((n3 + 255) / 256), 256>>>(w_proj, ws2, Dd, n3);
    }

    // 1) QKV = X @ Wattn^T
    {
        dim3 grid(D3 / 128, (Bb * Tt) / 128);
        gemm_fp16x2<<<grid, 256, GSMEM>>>(xs, ws1, qkv, Bb * Tt, D3, Dd);
    }

    // 2) fused rope + split + V transpose
    {
        dim3 grid(Tt / 64, Bb * Hh);
        convert_qkv<<<grid, 256>>>(rope);
    }

    // 3) mma flash attention -> split-fp16 output in g_as
    {
        dim3 grid(Tt / 128, Bb * Hh);
        attn_mma<<<grid, 256, ASMEM>>>(as_);
    }

    // 4) out = att @ Wproj^T
    {
        dim3 grid(Dd / 128, (Bb * Tt) / 128);
        gemm_fp16x2<<<grid, 256, GSMEM>>>(as_, ws2, out, Bb * Tt, Dd, Dd);
    }
}

// round 11
// speedup vs baseline: 1.5850x; 1.1267x over previous
#include <cuda_runtime.h>
#include <cuda_bf16.h>
#include <cuda_fp16.h>
#include <cstdint>
#include <math.h>

#define Bb 2
#define Tt 2048
#define Dd 2048
#define Hh 16
#define HD 128
#define HD2 64
#define D3 (3*Dd)

// ---------------- scratch (static device globals) ----------------------------
__device__ float g_qkv[(size_t)Bb*Tt*D3];                 // [B,T,(q|k|v),D]
__device__ __half g_xs [(size_t)Bb*Tt*2*Dd];              // x split fp16 [M, 2K]
__device__ __half g_as [(size_t)Bb*Tt*2*Dd];              // att split fp16 [M, 2K]
__device__ __half g_ws1[(size_t)D3*2*Dd];                 // w_attn split fp16 [N, 2K]
__device__ __half g_ws2[(size_t)Dd*2*Dd];                 // w_proj split fp16 [N, 2K]
__device__ __half g_qs [(size_t)Bb*Hh*Tt*HD];             // q roped+scaled fp16 (hi only)
__device__ __half g_ks [(size_t)Bb*Hh*Tt*HD];             // k roped fp16 (hi only)
__device__ __half g_vt [(size_t)Bb*Hh*HD*Tt];             // v^T fp16 [b,h,d,t]

// ---------------- PTX helpers ------------------------------------------------
__device__ __forceinline__ uint32_t smem_u32(const void* p) {
    uint32_t a;
    asm("{ .reg .u64 t; cvta.to.shared.u64 t, %1; cvt.u32.u64 %0, t; }"
        : "=r"(a) : "l"(p));
    return a;
}
__device__ __forceinline__ void cp16(uint32_t s, const void* g) {
    asm volatile("cp.async.cg.shared.global [%0], [%1], 16;" :: "r"(s), "l"(g));
}
#define CP_COMMIT() asm volatile("cp.async.commit_group;" ::: "memory")
#define CP_WAIT(n)  asm volatile("cp.async.wait_group %0;" :: "n"(n) : "memory")

#define LDSM4(r, a) \
    asm volatile("ldmatrix.sync.aligned.m8n8.x4.shared.b16 {%0,%1,%2,%3}, [%4];" \
        : "=r"((r)[0]), "=r"((r)[1]), "=r"((r)[2]), "=r"((r)[3]) : "r"(a))

#define MMA16816H(d, a, b0, b1) \
    asm volatile("mma.sync.aligned.m16n8k16.row.col.f32.f16.f16.f32 " \
        "{%0,%1,%2,%3}, {%4,%5,%6,%7}, {%8,%9}, {%0,%1,%2,%3};" \
        : "+f"((d)[0]), "+f"((d)[1]), "+f"((d)[2]), "+f"((d)[3]) \
        : "r"((a)[0]), "r"((a)[1]), "r"((a)[2]), "r"((a)[3]), "r"(b0), "r"(b1))

__device__ __forceinline__ uint32_t pk2h(float a, float b) {
    __half2 t = __floats2half2_rn(a, b);
    return *(uint32_t*)&t;
}

// ---------------- fp16x2 split: fp32 row[K] -> fp16 row[2K] ------------------
__global__ void split_fp16(const float* __restrict__ src,
                           __half* __restrict__ dst,
                           int Kdim, size_t total) {
    size_t idx = (size_t)blockIdx.x * blockDim.x + threadIdx.x;
    if (idx >= total) return;
    int k = (int)(idx % Kdim);
    size_t r = idx / Kdim;
    float x = src[idx];
    __half hi = __float2half_rn(x);
    __half lo = __float2half_rn(x - __half2float(hi));
    size_t o = r * (size_t)(2 * Kdim) + (size_t)(k >> 4) * 32 + (k & 15);
    dst[o] = hi;
    dst[o + 16] = lo;
}

// ---------------- fp16 2-product mma.sync GEMM (unchanged from R10) ----------
#define GSTAGE 32768
#define GSMEM  (3*GSTAGE)

__global__ __launch_bounds__(256, 2)
void gemm_fp16x2(const __half* __restrict__ Asp,
                 const __half* __restrict__ Bsp,
                 float* __restrict__ C, int M, int N, int K) {
    extern __shared__ char smc[];
    const uint32_t sb = smem_u32(smc);
    const int tid = threadIdx.x, lane = tid & 31, wid = tid >> 5;
    const int bm = blockIdx.y * 128, bn = blockIdx.x * 128;
    const int wm = (wid & 3) * 32, wn = (wid >> 2) * 64;
    const size_t K2 = (size_t)2 * K;
    const int NCH = K / 32;

    float acc[2][8][4];
#pragma unroll
    for (int mt = 0; mt < 2; mt++)
#pragma unroll
        for (int nt = 0; nt < 8; nt++)
#pragma unroll
            for (int e = 0; e < 4; e++) acc[mt][nt][e] = 0.f;

    auto load = [&](int ch, int s) {
        const uint32_t sA = sb + s * GSTAGE;
#pragma unroll
        for (int i = 0; i < 4; i++) {
            int id = tid + i * 256, r = id >> 3, u = id & 7;
            cp16(sA + r * 128 + ((u ^ (r & 7)) << 4),
                 Asp + (size_t)(bm + r) * K2 + ch * 64 + u * 8);
        }
        const uint32_t sB = sA + 16384;
#pragma unroll
        for (int i = 0; i < 4; i++) {
            int id = tid + i * 256, r = id >> 3, u = id & 7;
            cp16(sB + r * 128 + ((u ^ (r & 7)) << 4),
                 Bsp + (size_t)(bn + r) * K2 + ch * 64 + u * 8);
        }
    };

    load(0, 0); CP_COMMIT();
    load(1, 1); CP_COMMIT();

    for (int i = 0; i < NCH; i++) {
        if (i + 2 < NCH) load(i + 2, (i + 2) % 3);
        CP_COMMIT();
        CP_WAIT(2);
        __syncthreads();

        const uint32_t sA = sb + (i % 3) * GSTAGE;
        const uint32_t sB = sA + 16384;
#pragma unroll
        for (int sub = 0; sub < 2; sub++) {
            const int ubh = sub * 4, ubl = sub * 4 + 2;
            uint32_t Ah[2][4], Al[2][4];
#pragma unroll
            for (int mt = 0; mt < 2; mt++) {
                int row = wm + mt * 16 + (lane & 15);
                int uh = ubh + ((lane >> 4) & 1);
                LDSM4(Ah[mt], sA + row * 128 + ((uh ^ (row & 7)) << 4));
                int ul = ubl + ((lane >> 4) & 1);
                LDSM4(Al[mt], sA + row * 128 + ((ul ^ (row & 7)) << 4));
            }
#pragma unroll
            for (int ntp = 0; ntp < 4; ntp++) {
                int nrow = wn + ntp * 16 + (lane & 7) + ((lane >> 4) & 1) * 8;
                uint32_t Bh[4];
                int ukh = ubh + ((lane >> 3) & 1);
                LDSM4(Bh, sB + nrow * 128 + ((ukh ^ (nrow & 7)) << 4));
#pragma unroll
                for (int mt = 0; mt < 2; mt++)
#pragma unroll
                    for (int t = 0; t < 2; t++) {
                        float* d = acc[mt][ntp * 2 + t];
                        MMA16816H(d, Ah[mt], Bh[2 * t], Bh[2 * t + 1]);
                        MMA16816H(d, Al[mt], Bh[2 * t], Bh[2 * t + 1]);
                    }
            }
        }
        __syncthreads();
    }

#pragma unroll
    for (int mt = 0; mt < 2; mt++) {
        int r0 = bm + wm + mt * 16 + (lane >> 2);
#pragma unroll
        for (int nt = 0; nt < 8; nt++) {
            int c = bn + wn + nt * 8 + (lane & 3) * 2;
            float2 v0 = make_float2(acc[mt][nt][0], acc[mt][nt][1]);
            float2 v1 = make_float2(acc[mt][nt][2], acc[mt][nt][3]);
            *(float2*)&C[(size_t)r0 * N + c] = v0;
            *(float2*)&C[(size_t)(r0 + 8) * N + c] = v1;
        }
    }
}

// ---------------- fused rope + hi-fp16 + V-transpose -------------------------
// q/k: plain fp16 rows [t][128] (hi only; q pre-scaled). v^T: [d][t] fp16.
__global__ __launch_bounds__(256)
void convert_qkv(const float* __restrict__ rope) {
    __shared__ float vs[64][129];
    const int bh = blockIdx.y, b = bh >> 4, h = bh & 15;
    const int t0 = blockIdx.x * 64;
    const int tid = threadIdx.x;
    const int tl = tid >> 2, dbase = (tid & 3) * 32;
    const int t = t0 + tl;
    const float scale = 0.08838834764831845f;

    const float* qsrc = g_qkv + ((size_t)(b * Tt + t) * 3 + 0) * Dd + h * HD + dbase;
    const float* ksrc = qsrc + Dd;
    const float* vsrc = qsrc + 2 * Dd;
    __half* qdst = g_qs + ((size_t)bh * Tt + t) * HD;
    __half* kdst = g_ks + ((size_t)bh * Tt + t) * HD;

#pragma unroll
    for (int i = 0; i < 16; i++) {
        int d = dbase + 2 * i;
        float cr = rope[((size_t)t * 64 + (d >> 1)) * 2 + 0];
        float ci = rope[((size_t)t * 64 + (d >> 1)) * 2 + 1];

        float xr = qsrc[2 * i], xi = qsrc[2 * i + 1];
        *(uint32_t*)&qdst[d] = pk2h((xr * cr - xi * ci) * scale,
                                    (xi * cr + xr * ci) * scale);

        float yr = ksrc[2 * i], yi = ksrc[2 * i + 1];
        *(uint32_t*)&kdst[d] = pk2h(yr * cr - yi * ci,
                                    yi * cr + yr * ci);

        vs[tl][d] = vsrc[2 * i];
        vs[tl][d + 1] = vsrc[2 * i + 1];
    }
    __syncthreads();

    const int dl = tid & 127, th = tid >> 7;
    __half* vdst = g_vt + ((size_t)bh * 128 + dl) * Tt + t0;
#pragma unroll
    for (int j = 0; j < 16; j++) {
        int tloc = th * 32 + 2 * j;
        *(uint32_t*)&vdst[tloc] = pk2h(vs[tloc][dl], vs[tloc + 1][dl]);
    }
}

// ---------------- mma flash attention (all-fp16, 2 CTAs/SM) ------------------
// Q/K rows: 256B = two 128B swizzle halves; unit uu of row r at
//   r*256 + ((uu>>3)<<7) + (((uu&7) ^ (r&7)) << 4)
// smem: Q 32K | K 2x16K | V 2x16K | P 16K = 112KB -> 2 CTAs/SM
#define ASQ 0
#define ASK 32768
#define ASV 65536
#define ASP 98304
#define ASMEM 114688

__global__ __launch_bounds__(256, 2)
void attn_mma(__half* __restrict__ outs /* g_as */) {
    extern __shared__ char smc[];
    const uint32_t sb = smem_u32(smc);
    const int tid = threadIdx.x, lane = tid & 31, wid = tid >> 5;
    const int wm = wid & 3, wn = wid >> 2;
    const int qt = gridDim.x - 1 - blockIdx.x;
    const int bh = blockIdx.y, b = bh >> 4, h = bh & 15;
    const int q0 = qt * 128;
    const int nkt = 2 * (qt + 1);

    const __half* Qg = g_qs + ((size_t)bh * Tt + q0) * HD;
    const __half* Kg = g_ks + (size_t)bh * Tt * HD;
    const __half* Vg = g_vt + (size_t)bh * 128 * Tt;

    {
        // Q: 128 rows x 16 units
#pragma unroll
        for (int i = 0; i < 8; i++) {
            int id = tid + i * 256, r = id >> 4, u = id & 15;
            cp16(sb + ASQ + r * 256 + ((u >> 3) << 7) + (((u & 7) ^ (r & 7)) << 4),
                 Qg + (size_t)r * HD + u * 8);
        }
        // K0: 64 rows x 16 units
#pragma unroll
        for (int i = 0; i < 4; i++) {
            int id = tid + i * 256, r = id >> 4, u = id & 15;
            cp16(sb + ASK + r * 256 + ((u >> 3) << 7) + (((u & 7) ^ (r & 7)) << 4),
                 Kg + (size_t)r * HD + u * 8);
        }
        // V0: 128 d-rows x 8 units
#pragma unroll
        for (int i = 0; i < 4; i++) {
            int id = tid + i * 256, r = id >> 3, u = id & 7;
            cp16(sb + ASV + r * 128 + ((u ^ (r & 7)) << 4), Vg + (size_t)r * Tt + u * 8);
        }
        CP_COMMIT();
    }

    float oacc[2][8][4];
#pragma unroll
    for (int mt = 0; mt < 2; mt++)
#pragma unroll
        for (int nt = 0; nt < 8; nt++)
#pragma unroll
            for (int e = 0; e < 4; e++) oacc[mt][nt][e] = 0.f;
    float lp[4] = {0.f, 0.f, 0.f, 0.f};

    for (int kt = 0; kt < nkt; kt++) {
        const int s = kt & 1;
        CP_WAIT(0);
        __syncthreads();

        if (kt + 1 < nkt) {
            const __half* Kn = Kg + (size_t)(kt + 1) * 64 * HD;
            const uint32_t dk = sb + ASK + (s ^ 1) * 16384;
#pragma unroll
            for (int i = 0; i < 4; i++) {
                int id = tid + i * 256, r = id >> 4, u = id & 15;
                cp16(dk + r * 256 + ((u >> 3) << 7) + (((u & 7) ^ (r & 7)) << 4),
                     Kn + (size_t)r * HD + u * 8);
            }
            const uint32_t dv = sb + ASV + (s ^ 1) * 16384;
#pragma unroll
            for (int i = 0; i < 4; i++) {
                int id = tid + i * 256, r = id >> 3, u = id & 7;
                cp16(dv + r * 128 + ((u ^ (r & 7)) << 4),
                     Vg + (size_t)r * Tt + (kt + 1) * 64 + u * 8);
            }
            CP_COMMIT();
        }

        // ---- S = Q @ K^T (single fp16 product) ----
        float sacc[2][4][4];
#pragma unroll
        for (int mt = 0; mt < 2; mt++)
#pragma unroll
            for (int nt = 0; nt < 4; nt++)
#pragma unroll
                for (int e = 0; e < 4; e++) sacc[mt][nt][e] = 0.f;

        const uint32_t sq = sb + ASQ, sk = sb + ASK + s * 16384;
#pragma unroll
        for (int gd = 0; gd < 8; gd++) {
            uint32_t Ah[2][4];
#pragma unroll
            for (int mt = 0; mt < 2; mt++) {
                int r = wm * 32 + mt * 16 + (lane & 15);
                int uu = gd * 2 + ((lane >> 4) & 1);
                LDSM4(Ah[mt], sq + r * 256 + ((uu >> 3) << 7) + (((uu & 7) ^ (r & 7)) << 4));
            }
#pragma unroll
            for (int ntp = 0; ntp < 2; ntp++) {
                int nr = wn * 32 + ntp * 16 + (lane & 7) + ((lane >> 4) & 1) * 8;
                uint32_t Bh[4];
                int uu = gd * 2 + ((lane >> 3) & 1);
                LDSM4(Bh, sk + nr * 256 + ((uu >> 3) << 7) + (((uu & 7) ^ (nr & 7)) << 4));
#pragma unroll
                for (int mt = 0; mt < 2; mt++)
#pragma unroll
                    for (int t = 0; t < 2; t++)
                        MMA16816H(sacc[mt][ntp * 2 + t], Ah[mt], Bh[2 * t], Bh[2 * t + 1]);
            }
        }

        // ---- exp + causal + store P (fp16, 128B rows) ----
        const bool edge = (kt >= nkt - 2);
#pragma unroll
        for (int mt = 0; mt < 2; mt++) {
            int r0 = wm * 32 + mt * 16 + (lane >> 2);
#pragma unroll
            for (int n8 = 0; n8 < 4; n8++) {
                int c0 = wn * 32 + n8 * 8 + (lane & 3) * 2;
                float e00 = __expf(sacc[mt][n8][0]);
                float e01 = __expf(sacc[mt][n8][1]);
                float e10 = __expf(sacc[mt][n8][2]);
                float e11 = __expf(sacc[mt][n8][3]);
                if (edge) {
                    int cg = kt * 64 + c0;
                    if (cg     > q0 + r0)     e00 = 0.f;
                    if (cg + 1 > q0 + r0)     e01 = 0.f;
                    if (cg     > q0 + r0 + 8) e10 = 0.f;
                    if (cg + 1 > q0 + r0 + 8) e11 = 0.f;
                }
                lp[mt * 2 + 0] += e00 + e01;
                lp[mt * 2 + 1] += e10 + e11;

                int uh = c0 >> 3;
                int boff = (c0 & 7) * 2;
                *(uint32_t*)(smc + ASP + r0 * 128 + ((uh ^ (r0 & 7)) << 4) + boff) = pk2h(e00, e01);
                int r1 = r0 + 8;
                *(uint32_t*)(smc + ASP + r1 * 128 + ((uh ^ (r1 & 7)) << 4) + boff) = pk2h(e10, e11);
            }
        }
        __syncthreads();

        // ---- O += P @ V^T (single fp16 product) ----
        const uint32_t sp = sb + ASP, sv = sb + ASV + s * 16384;
#pragma unroll
        for (int gt = 0; gt < 4; gt++) {
            uint32_t Ph[2][4];
#pragma unroll
            for (int mt = 0; mt < 2; mt++) {
                int r = wm * 32 + mt * 16 + (lane & 15);
                int uh = gt * 2 + ((lane >> 4) & 1);
                LDSM4(Ph[mt], sp + r * 128 + ((uh ^ (r & 7)) << 4));
            }
#pragma unroll
            for (int ntp = 0; ntp < 4; ntp++) {
                int nr = wn * 64 + ntp * 16 + (lane & 7) + ((lane >> 4) & 1) * 8;
                uint32_t Vh[4];
                int uk = gt * 2 + ((lane >> 3) & 1);
                LDSM4(Vh, sv + nr * 128 + ((uk ^ (nr & 7)) << 4));
#pragma unroll
                for (int mt = 0; mt < 2; mt++)
#pragma unroll
                    for (int t = 0; t < 2; t++)
                        MMA16816H(oacc[mt][ntp * 2 + t], Ph[mt], Vh[2 * t], Vh[2 * t + 1]);
            }
        }
        __syncthreads();
    }

    // ---- l reduce ----
#pragma unroll
    for (int sl = 0; sl < 4; sl++) {
        float v = lp[sl];
        v += __shfl_xor_sync(0xffffffffu, v, 1);
        v += __shfl_xor_sync(0xffffffffu, v, 2);
        lp[sl] = v;
    }
    __syncthreads();
    float* lred = (float*)(smc + ASP);
    if ((lane & 3) == 0) {
#pragma unroll
        for (int mt = 0; mt < 2; mt++)
#pragma unroll
            for (int rh = 0; rh < 2; rh++) {
                int r = wm * 32 + mt * 16 + rh * 8 + (lane >> 2);
                lred[r * 2 + wn] = lp[mt * 2 + rh];
            }
    }
    __syncthreads();

    // ---- normalize + write split-fp16 directly to g_as ----
#pragma unroll
    for (int mt = 0; mt < 2; mt++)
#pragma unroll
        for (int rh = 0; rh < 2; rh++) {
            int r = wm * 32 + mt * 16 + rh * 8 + (lane >> 2);
            float inv = 1.0f / (lred[r * 2] + lred[r * 2 + 1]);
            __half* dst = outs + (size_t)(b * Tt + q0 + r) * (2 * Dd);
#pragma unroll
            for (int n8 = 0; n8 < 8; n8++) {
                int c = wn * 64 + n8 * 8 + (lane & 3) * 2;
                float o0 = oacc[mt][n8][rh * 2 + 0] * inv;
                float o1 = oacc[mt][n8][rh * 2 + 1] * inv;
                __half b0 = __float2half_rn(o0);
                __half b1 = __float2half_rn(o1);
                int gcol = h * 128 + c;
                size_t o = (size_t)(gcol >> 4) * 32 + (gcol & 15);
                *(uint32_t*)&dst[o] = pk2h(o0, o1);
                *(uint32_t*)&dst[o + 16] =
                    pk2h(o0 - __half2float(b0), o1 - __half2float(b1));
            }
        }
}

// ---------------- launcher --------------------------------------------------
extern "C" void kernel_launch(void* const* d_in, const int* in_sizes, int n_in,
                              void* d_out, int out_size) {
    (void)in_sizes; (void)n_in; (void)out_size;
    const float* x      = (const float*)d_in[0];
    const float* rope   = (const float*)d_in[1];
    const float* w_attn = (const float*)d_in[3];
    const float* w_proj = (const float*)d_in[4];
    float* out = (float*)d_out;

    float* qkv;
    __half *xs, *as_, *ws1, *ws2;
    cudaGetSymbolAddress((void**)&qkv, g_qkv);
    cudaGetSymbolAddress((void**)&xs,  g_xs);
    cudaGetSymbolAddress((void**)&as_, g_as);
    cudaGetSymbolAddress((void**)&ws1, g_ws1);
    cudaGetSymbolAddress((void**)&ws2, g_ws2);

    cudaFuncSetAttribute(gemm_fp16x2,
                         cudaFuncAttributeMaxDynamicSharedMemorySize, GSMEM);
    cudaFuncSetAttribute(attn_mma,
                         cudaFuncAttributeMaxDynamicSharedMemorySize, ASMEM);

    // splits
    {
        size_t n1 = (size_t)Bb * Tt * Dd;
        split_fp16<<<(unsigned)((n1 + 255) / 256), 256>>>(x, xs, Dd, n1);
        size_t n2 = (size_t)D3 * Dd;
        split_fp16<<<(unsigned)((n2 + 255) / 256), 256>>>(w_attn, ws1, Dd, n2);
        size_t n3 = (size_t)Dd * Dd;
        split_fp16<<<(unsigned)((n3 + 255) / 256), 256>>>(w_proj, ws2, Dd, n3);
    }

    // 1) QKV = X @ Wattn^T
    {
        dim3 grid(D3 / 128, (Bb * Tt) / 128);
        gemm_fp16x2<<<grid, 256, GSMEM>>>(xs, ws1, qkv, Bb * Tt, D3, Dd);
    }

    // 2) fused rope + hi-fp16 + V transpose
    {
        dim3 grid(Tt / 64, Bb * Hh);
        convert_qkv<<<grid, 256>>>(rope);
    }

    // 3) mma flash attention (2 CTAs/SM) -> split-fp16 output in g_as
    {
        dim3 grid(Tt / 128, Bb * Hh);
        attn_mma<<<grid, 256, ASMEM>>>(as_);
    }

    // 4) out = att @ Wproj^T
    {
        dim3 grid(Dd / 128, (Bb * Tt) / 128);
        gemm_fp16x2<<<grid, 256, GSMEM>>>(as_, ws2, out, Bb * Tt, Dd, Dd);
    }
}

// round 14
// speedup vs baseline: 2.2980x; 1.4499x over previous
#include <cuda_runtime.h>
#include <cuda_bf16.h>
#include <cuda_fp16.h>
#include <cstdint>
#include <math.h>

#define Bb 2
#define Tt 2048
#define Dd 2048
#define Hh 16
#define HD 128
#define HD2 64
#define D3 (3*Dd)

// ---------------- scratch (static device globals) ----------------------------
__device__ float g_qkv[(size_t)Bb*Tt*D3];                 // [B,T,(q|k|v),D]
__device__ __half g_xh [(size_t)Bb*Tt*Dd];                // x fp16 [M, K]
__device__ __half g_ah [(size_t)Bb*Tt*Dd];                // att fp16 [M, K]
__device__ __half g_wh1[(size_t)D3*Dd];                   // w_attn fp16 [N, K]
__device__ __half g_wh2[(size_t)Dd*Dd];                   // w_proj fp16 [N, K]
__device__ __half g_qs [(size_t)Bb*Hh*Tt*HD];             // q roped+scaled fp16
__device__ __half g_ks [(size_t)Bb*Hh*Tt*HD];             // k roped fp16
__device__ __half g_vt [(size_t)Bb*Hh*HD*Tt];             // v^T fp16 [b,h,d,t]

// ---------------- PTX helpers ------------------------------------------------
__device__ __forceinline__ uint32_t smem_u32(const void* p) {
    uint32_t a;
    asm("{ .reg .u64 t; cvta.to.shared.u64 t, %1; cvt.u32.u64 %0, t; }"
        : "=r"(a) : "l"(p));
    return a;
}
__device__ __forceinline__ void cp16(uint32_t s, const void* g) {
    asm volatile("cp.async.cg.shared.global [%0], [%1], 16;" :: "r"(s), "l"(g));
}
#define CP_COMMIT() asm volatile("cp.async.commit_group;" ::: "memory")
#define CP_WAIT(n)  asm volatile("cp.async.wait_group %0;" :: "n"(n) : "memory")

#define LDSM4(r, a) \
    asm volatile("ldmatrix.sync.aligned.m8n8.x4.shared.b16 {%0,%1,%2,%3}, [%4];" \
        : "=r"((r)[0]), "=r"((r)[1]), "=r"((r)[2]), "=r"((r)[3]) : "r"(a))

#define MMA16816H(d, a, b0, b1) \
    asm volatile("mma.sync.aligned.m16n8k16.row.col.f32.f16.f16.f32 " \
        "{%0,%1,%2,%3}, {%4,%5,%6,%7}, {%8,%9}, {%0,%1,%2,%3};" \
        : "+f"((d)[0]), "+f"((d)[1]), "+f"((d)[2]), "+f"((d)[3]) \
        : "r"((a)[0]), "r"((a)[1]), "r"((a)[2]), "r"((a)[3]), "r"(b0), "r"(b1))

__device__ __forceinline__ uint32_t pk2h(float a, float b) {
    __half2 t = __floats2half2_rn(a, b);
    return *(uint32_t*)&t;
}

// ---------------- fp32 -> fp16 cast (vectorized) ------------------------------
__global__ void conv_fp16(const float* __restrict__ src,
                          __half* __restrict__ dst, size_t total2) {
    size_t idx = (size_t)blockIdx.x * blockDim.x + threadIdx.x;
    if (idx >= total2) return;
    float2 v = ((const float2*)src)[idx];
    ((uint32_t*)dst)[idx] = pk2h(v.x, v.y);
}

// ---------------- fp16 single-product mma.sync GEMM --------------------------
// C[M,N] = A[M,K] @ B[N,K]^T, plain fp16 operands.
// 128x128 tile, 256 threads, K-chunk 64 (128B rows), 3 stages x 32KB.
#define GSTAGE 32768
#define GSMEM  (3*GSTAGE)

__global__ __launch_bounds__(256, 2)
void gemm_fp16(const __half* __restrict__ A, const __half* __restrict__ B,
               float* __restrict__ C, int M, int N, int K) {
    extern __shared__ char smc[];
    const uint32_t sb = smem_u32(smc);
    const int tid = threadIdx.x, lane = tid & 31, wid = tid >> 5;
    const int bm = blockIdx.y * 128, bn = blockIdx.x * 128;
    const int wm = (wid & 3) * 32, wn = (wid >> 2) * 64;
    const int NCH = K / 64;

    float acc[2][8][4];
#pragma unroll
    for (int mt = 0; mt < 2; mt++)
#pragma unroll
        for (int nt = 0; nt < 8; nt++)
#pragma unroll
            for (int e = 0; e < 4; e++) acc[mt][nt][e] = 0.f;

    auto load = [&](int ch, int s) {
        const uint32_t sA = sb + s * GSTAGE;
#pragma unroll
        for (int i = 0; i < 4; i++) {
            int id = tid + i * 256, r = id >> 3, u = id & 7;
            cp16(sA + r * 128 + ((u ^ (r & 7)) << 4),
                 A + (size_t)(bm + r) * K + ch * 64 + u * 8);
        }
        const uint32_t sB = sA + 16384;
#pragma unroll
        for (int i = 0; i < 4; i++) {
            int id = tid + i * 256, r = id >> 3, u = id & 7;
            cp16(sB + r * 128 + ((u ^ (r & 7)) << 4),
                 B + (size_t)(bn + r) * K + ch * 64 + u * 8);
        }
    };

    load(0, 0); CP_COMMIT();
    load(1, 1); CP_COMMIT();

    for (int i = 0; i < NCH; i++) {
        if (i + 2 < NCH) load(i + 2, (i + 2) % 3);
        CP_COMMIT();
        CP_WAIT(2);
        __syncthreads();

        const uint32_t sA = sb + (i % 3) * GSTAGE;
        const uint32_t sB = sA + 16384;
#pragma unroll
        for (int gd = 0; gd < 4; gd++) {
            uint32_t Ah[2][4];
#pragma unroll
            for (int mt = 0; mt < 2; mt++) {
                int row = wm + mt * 16 + (lane & 15);
                int uh = gd * 2 + ((lane >> 4) & 1);
                LDSM4(Ah[mt], sA + row * 128 + ((uh ^ (row & 7)) << 4));
            }
#pragma unroll
            for (int ntp = 0; ntp < 4; ntp++) {
                int nrow = wn + ntp * 16 + (lane & 7) + ((lane >> 4) & 1) * 8;
                uint32_t Bh[4];
                int uk = gd * 2 + ((lane >> 3) & 1);
                LDSM4(Bh, sB + nrow * 128 + ((uk ^ (nrow & 7)) << 4));
#pragma unroll
                for (int mt = 0; mt < 2; mt++)
#pragma unroll
                    for (int t = 0; t < 2; t++)
                        MMA16816H(acc[mt][ntp * 2 + t], Ah[mt], Bh[2 * t], Bh[2 * t + 1]);
            }
        }
        __syncthreads();
    }

#pragma unroll
    for (int mt = 0; mt < 2; mt++) {
        int r0 = bm + wm + mt * 16 + (lane >> 2);
#pragma unroll
        for (int nt = 0; nt < 8; nt++) {
            int c = bn + wn + nt * 8 + (lane & 3) * 2;
            float2 v0 = make_float2(acc[mt][nt][0], acc[mt][nt][1]);
            float2 v1 = make_float2(acc[mt][nt][2], acc[mt][nt][3]);
            *(float2*)&C[(size_t)r0 * N + c] = v0;
            *(float2*)&C[(size_t)(r0 + 8) * N + c] = v1;
        }
    }
}

// ---------------- fused rope + hi-fp16 + V-transpose -------------------------
__global__ __launch_bounds__(256)
void convert_qkv(const float* __restrict__ rope) {
    __shared__ float vs[64][129];
    const int bh = blockIdx.y, b = bh >> 4, h = bh & 15;
    const int t0 = blockIdx.x * 64;
    const int tid = threadIdx.x;
    const int tl = tid >> 2, dbase = (tid & 3) * 32;
    const int t = t0 + tl;
    const float scale = 0.08838834764831845f;

    const float* qsrc = g_qkv + ((size_t)(b * Tt + t) * 3 + 0) * Dd + h * HD + dbase;
    const float* ksrc = qsrc + Dd;
    const float* vsrc = qsrc + 2 * Dd;
    __half* qdst = g_qs + ((size_t)bh * Tt + t) * HD;
    __half* kdst = g_ks + ((size_t)bh * Tt + t) * HD;

#pragma unroll
    for (int i = 0; i < 16; i++) {
        int d = dbase + 2 * i;
        float cr = rope[((size_t)t * 64 + (d >> 1)) * 2 + 0];
        float ci = rope[((size_t)t * 64 + (d >> 1)) * 2 + 1];

        float xr = qsrc[2 * i], xi = qsrc[2 * i + 1];
        *(uint32_t*)&qdst[d] = pk2h((xr * cr - xi * ci) * scale,
                                    (xi * cr + xr * ci) * scale);

        float yr = ksrc[2 * i], yi = ksrc[2 * i + 1];
        *(uint32_t*)&kdst[d] = pk2h(yr * cr - yi * ci,
                                    yi * cr + yr * ci);

        vs[tl][d] = vsrc[2 * i];
        vs[tl][d + 1] = vsrc[2 * i + 1];
    }
    __syncthreads();

    const int dl = tid & 127, th = tid >> 7;
    __half* vdst = g_vt + ((size_t)bh * 128 + dl) * Tt + t0;
#pragma unroll
    for (int j = 0; j < 16; j++) {
        int tloc = th * 32 + 2 * j;
        *(uint32_t*)&vdst[tloc] = pk2h(vs[tloc][dl], vs[tloc + 1][dl]);
    }
}

// ---------------- mma flash attention (all-fp16, 2 CTAs/SM) ------------------
// smem: Q 32K | K 2x16K | V 2x16K | P 16K = 112KB
#define ASQ 0
#define ASK 32768
#define ASV 65536
#define ASP 98304
#define ASMEM 114688

__global__ __launch_bounds__(256, 2)
void attn_mma(__half* __restrict__ outs /* g_ah */) {
    extern __shared__ char smc[];
    const uint32_t sb = smem_u32(smc);
    const int tid = threadIdx.x, lane = tid & 31, wid = tid >> 5;
    const int wm = wid & 3, wn = wid >> 2;
    const int qt = gridDim.x - 1 - blockIdx.x;
    const int bh = blockIdx.y, b = bh >> 4, h = bh & 15;
    const int q0 = qt * 128;
    const int nkt = 2 * (qt + 1);

    const __half* Qg = g_qs + ((size_t)bh * Tt + q0) * HD;
    const __half* Kg = g_ks + (size_t)bh * Tt * HD;
    const __half* Vg = g_vt + (size_t)bh * 128 * Tt;

    {
#pragma unroll
        for (int i = 0; i < 8; i++) {
            int id = tid + i * 256, r = id >> 4, u = id & 15;
            cp16(sb + ASQ + r * 256 + ((u >> 3) << 7) + (((u & 7) ^ (r & 7)) << 4),
                 Qg + (size_t)r * HD + u * 8);
        }
#pragma unroll
        for (int i = 0; i < 4; i++) {
            int id = tid + i * 256, r = id >> 4, u = id & 15;
            cp16(sb + ASK + r * 256 + ((u >> 3) << 7) + (((u & 7) ^ (r & 7)) << 4),
                 Kg + (size_t)r * HD + u * 8);
        }
#pragma unroll
        for (int i = 0; i < 4; i++) {
            int id = tid + i * 256, r = id >> 3, u = id & 7;
            cp16(sb + ASV + r * 128 + ((u ^ (r & 7)) << 4), Vg + (size_t)r * Tt + u * 8);
        }
        CP_COMMIT();
    }

    float oacc[2][8][4];
#pragma unroll
    for (int mt = 0; mt < 2; mt++)
#pragma unroll
        for (int nt = 0; nt < 8; nt++)
#pragma unroll
            for (int e = 0; e < 4; e++) oacc[mt][nt][e] = 0.f;
    float lp[4] = {0.f, 0.f, 0.f, 0.f};

    for (int kt = 0; kt < nkt; kt++) {
        const int s = kt & 1;
        CP_WAIT(0);
        __syncthreads();

        if (kt + 1 < nkt) {
            const __half* Kn = Kg + (size_t)(kt + 1) * 64 * HD;
            const uint32_t dk = sb + ASK + (s ^ 1) * 16384;
#pragma unroll
            for (int i = 0; i < 4; i++) {
                int id = tid + i * 256, r = id >> 4, u = id & 15;
                cp16(dk + r * 256 + ((u >> 3) << 7) + (((u & 7) ^ (r & 7)) << 4),
                     Kn + (size_t)r * HD + u * 8);
            }
            const uint32_t dv = sb + ASV + (s ^ 1) * 16384;
#pragma unroll
            for (int i = 0; i < 4; i++) {
                int id = tid + i * 256, r = id >> 3, u = id & 7;
                cp16(dv + r * 128 + ((u ^ (r & 7)) << 4),
                     Vg + (size_t)r * Tt + (kt + 1) * 64 + u * 8);
            }
            CP_COMMIT();
        }

        // ---- S = Q @ K^T ----
        float sacc[2][4][4];
#pragma unroll
        for (int mt = 0; mt < 2; mt++)
#pragma unroll
            for (int nt = 0; nt < 4; nt++)
#pragma unroll
                for (int e = 0; e < 4; e++) sacc[mt][nt][e] = 0.f;

        const uint32_t sq = sb + ASQ, sk = sb + ASK + s * 16384;
#pragma unroll
        for (int gd = 0; gd < 8; gd++) {
            uint32_t Ah[2][4];
#pragma unroll
            for (int mt = 0; mt < 2; mt++) {
                int r = wm * 32 + mt * 16 + (lane & 15);
                int uu = gd * 2 + ((lane >> 4) & 1);
                LDSM4(Ah[mt], sq + r * 256 + ((uu >> 3) << 7) + (((uu & 7) ^ (r & 7)) << 4));
            }
#pragma unroll
            for (int ntp = 0; ntp < 2; ntp++) {
                int nr = wn * 32 + ntp * 16 + (lane & 7) + ((lane >> 4) & 1) * 8;
                uint32_t Bh[4];
                int uu = gd * 2 + ((lane >> 3) & 1);
                LDSM4(Bh, sk + nr * 256 + ((uu >> 3) << 7) + (((uu & 7) ^ (nr & 7)) << 4));
#pragma unroll
                for (int mt = 0; mt < 2; mt++)
#pragma unroll
                    for (int t = 0; t < 2; t++)
                        MMA16816H(sacc[mt][ntp * 2 + t], Ah[mt], Bh[2 * t], Bh[2 * t + 1]);
            }
        }

        // ---- exp + causal + store P (fp16) ----
        const bool edge = (kt >= nkt - 2);
#pragma unroll
        for (int mt = 0; mt < 2; mt++) {
            int r0 = wm * 32 + mt * 16 + (lane >> 2);
#pragma unroll
            for (int n8 = 0; n8 < 4; n8++) {
                int c0 = wn * 32 + n8 * 8 + (lane & 3) * 2;
                float e00 = __expf(sacc[mt][n8][0]);
                float e01 = __expf(sacc[mt][n8][1]);
                float e10 = __expf(sacc[mt][n8][2]);
                float e11 = __expf(sacc[mt][n8][3]);
                if (edge) {
                    int cg = kt * 64 + c0;
                    if (cg     > q0 + r0)     e00 = 0.f;
                    if (cg + 1 > q0 + r0)     e01 = 0.f;
                    if (cg     > q0 + r0 + 8) e10 = 0.f;
                    if (cg + 1 > q0 + r0 + 8) e11 = 0.f;
                }
                lp[mt * 2 + 0] += e00 + e01;
                lp[mt * 2 + 1] += e10 + e11;

                int uh = c0 >> 3;
                int boff = (c0 & 7) * 2;
                *(uint32_t*)(smc + ASP + r0 * 128 + ((uh ^ (r0 & 7)) << 4) + boff) = pk2h(e00, e01);
                int r1 = r0 + 8;
                *(uint32_t*)(smc + ASP + r1 * 128 + ((uh ^ (r1 & 7)) << 4) + boff) = pk2h(e10, e11);
            }
        }
        __syncthreads();

        // ---- O += P @ V^T ----
        const uint32_t sp = sb + ASP, sv = sb + ASV + s * 16384;
#pragma unroll
        for (int gt = 0; gt < 4; gt++) {
            uint32_t Ph[2][4];
#pragma unroll
            for (int mt = 0; mt < 2; mt++) {
                int r = wm * 32 + mt * 16 + (lane & 15);
                int uh = gt * 2 + ((lane >> 4) & 1);
                LDSM4(Ph[mt], sp + r * 128 + ((uh ^ (r & 7)) << 4));
            }
#pragma unroll
            for (int ntp = 0; ntp < 4; ntp++) {
                int nr = wn * 64 + ntp * 16 + (lane & 7) + ((lane >> 4) & 1) * 8;
                uint32_t Vh[4];
                int uk = gt * 2 + ((lane >> 3) & 1);
                LDSM4(Vh, sv + nr * 128 + ((uk ^ (nr & 7)) << 4));
#pragma unroll
                for (int mt = 0; mt < 2; mt++)
#pragma unroll
                    for (int t = 0; t < 2; t++)
                        MMA16816H(oacc[mt][ntp * 2 + t], Ph[mt], Vh[2 * t], Vh[2 * t + 1]);
            }
        }
        __syncthreads();
    }

    // ---- l reduce ----
#pragma unroll
    for (int sl = 0; sl < 4; sl++) {
        float v = lp[sl];
        v += __shfl_xor_sync(0xffffffffu, v, 1);
        v += __shfl_xor_sync(0xffffffffu, v, 2);
        lp[sl] = v;
    }
    __syncthreads();
    float* lred = (float*)(smc + ASP);
    if ((lane & 3) == 0) {
#pragma unroll
        for (int mt = 0; mt < 2; mt++)
#pragma unroll
            for (int rh = 0; rh < 2; rh++) {
                int r = wm * 32 + mt * 16 + rh * 8 + (lane >> 2);
                lred[r * 2 + wn] = lp[mt * 2 + rh];
            }
    }
    __syncthreads();

    // ---- normalize + write plain fp16 to g_ah ----
#pragma unroll
    for (int mt = 0; mt < 2; mt++)
#pragma unroll
        for (int rh = 0; rh < 2; rh++) {
            int r = wm * 32 + mt * 16 + rh * 8 + (lane >> 2);
            float inv = 1.0f / (lred[r * 2] + lred[r * 2 + 1]);
            __half* dst = outs + (size_t)(b * Tt + q0 + r) * Dd + h * HD;
#pragma unroll
            for (int n8 = 0; n8 < 8; n8++) {
                int c = wn * 64 + n8 * 8 + (lane & 3) * 2;
                *(uint32_t*)&dst[c] = pk2h(oacc[mt][n8][rh * 2 + 0] * inv,
                                           oacc[mt][n8][rh * 2 + 1] * inv);
            }
        }
}

// ---------------- launcher --------------------------------------------------
extern "C" void kernel_launch(void* const* d_in, const int* in_sizes, int n_in,
                              void* d_out, int out_size) {
    (void)in_sizes; (void)n_in; (void)out_size;
    const float* x      = (const float*)d_in[0];
    const float* rope   = (const float*)d_in[1];
    const float* w_attn = (const float*)d_in[3];
    const float* w_proj = (const float*)d_in[4];
    float* out = (float*)d_out;

    float* qkv;
    __half *xh, *ah, *wh1, *wh2;
    cudaGetSymbolAddress((void**)&qkv, g_qkv);
    cudaGetSymbolAddress((void**)&xh,  g_xh);
    cudaGetSymbolAddress((void**)&ah,  g_ah);
    cudaGetSymbolAddress((void**)&wh1, g_wh1);
    cudaGetSymbolAddress((void**)&wh2, g_wh2);

    cudaFuncSetAttribute(gemm_fp16,
                         cudaFuncAttributeMaxDynamicSharedMemorySize, GSMEM);
    cudaFuncSetAttribute(attn_mma,
                         cudaFuncAttributeMaxDynamicSharedMemorySize, ASMEM);

    // fp16 casts
    {
        size_t n1 = (size_t)Bb * Tt * Dd / 2;
        conv_fp16<<<(unsigned)((n1 + 255) / 256), 256>>>(x, xh, n1);
        size_t n2 = (size_t)D3 * Dd / 2;
        conv_fp16<<<(unsigned)((n2 + 255) / 256), 256>>>(w_attn, wh1, n2);
        size_t n3 = (size_t)Dd * Dd / 2;
        conv_fp16<<<(unsigned)((n3 + 255) / 256), 256>>>(w_proj, wh2, n3);
    }

    // 1) QKV = X @ Wattn^T
    {
        dim3 grid(D3 / 128, (Bb * Tt) / 128);
        gemm_fp16<<<grid, 256, GSMEM>>>(xh, wh1, qkv, Bb * Tt, D3, Dd);
    }

    // 2) fused rope + hi-fp16 + V transpose
    {
        dim3 grid(Tt / 64, Bb * Hh);
        convert_qkv<<<grid, 256>>>(rope);
    }

    // 3) mma flash attention (2 CTAs/SM) -> fp16 output in g_ah
    {
        dim3 grid(Tt / 128, Bb * Hh);
        attn_mma<<<grid, 256, ASMEM>>>(ah);
    }

    // 4) out = att @ Wproj^T
    {
        dim3 grid(Dd / 128, (Bb * Tt) / 128);
        gemm_fp16<<<grid, 256, GSMEM>>>(ah, wh2, out, Bb * Tt, Dd, Dd);
    }
}